// round 11
// baseline (speedup 1.0000x reference)
#include <cuda_runtime.h>
#include <mma.h>
#include <math.h>
using namespace nvcuda;

#define Bb 4
#define Ss 2048
#define Dd 512
#define Hh 8

// ---------------- scratch ---------------------------------------------------
__device__ float g_xn [Bb*Ss*Dd];
__device__ float g_q  [Bb*Ss*Dd];
__device__ float g_k  [Bb*Ss*Dd];
__device__ float g_v  [Bb*Ss*Dd];
__device__ float g_ctx[Bb*Ss*Dd];
__device__ float g_pe [Ss*Dd];
__device__ float g_pos[Ss*Dd];
__device__ float g_ps [(size_t)Bb*Hh*Ss*Ss];   // raw position scores
__device__ float g_p  [(size_t)Bb*Hh*Ss*Ss];   // P = exp(score) (un-normalized)
__device__ float g_lp [Bb*Hh*Ss*16];           // partial row sums per t-tile

__device__ __forceinline__ float f2t(float x) {
    unsigned r; asm("cvt.rna.tf32.f32 %0, %1;" : "=r"(r) : "f"(x));
    return __uint_as_float(r);
}

// ---------------- sinusoidal positional encoding ---------------------------
__global__ void pe_kernel(float* __restrict__ pe) {
    int idx = blockIdx.x * blockDim.x + threadIdx.x;
    int s = idx >> 8;
    int i = idx & 255;
    float div = expf((2.0f * (float)i) * (-9.210340371976184f / 512.0f));
    float a = (float)s * div;
    pe[s * Dd + 2 * i]     = sinf(a);
    pe[s * Dd + 2 * i + 1] = cosf(a);
}

// ---------------- layernorm -------------------------------------------------
__global__ void ln_kernel(const float* __restrict__ x,
                          const float* __restrict__ gamma,
                          const float* __restrict__ beta,
                          float* __restrict__ out) {
    int row = blockIdx.x;
    const float2* xr = (const float2*)(x + (size_t)row * Dd);
    int t = threadIdx.x;
    float2 v = xr[t];
    float s1 = v.x + v.y;
    float s2 = v.x * v.x + v.y * v.y;
    #pragma unroll
    for (int o = 16; o; o >>= 1) {
        s1 += __shfl_xor_sync(0xffffffffu, s1, o);
        s2 += __shfl_xor_sync(0xffffffffu, s2, o);
    }
    __shared__ float r1[8], r2[8];
    if ((t & 31) == 0) { r1[t >> 5] = s1; r2[t >> 5] = s2; }
    __syncthreads();
    float S1 = 0.f, S2 = 0.f;
    #pragma unroll
    for (int i = 0; i < 8; i++) { S1 += r1[i]; S2 += r2[i]; }
    float mean = S1 * (1.0f / 512.0f);
    float var  = S2 * (1.0f / 512.0f) - mean * mean;
    float rstd = rsqrtf(var + 1e-5f);
    float2 g  = ((const float2*)gamma)[t];
    float2 bt = ((const float2*)beta)[t];
    float2 o2;
    o2.x = (v.x - mean) * rstd * g.x + bt.x;
    o2.y = (v.y - mean) * rstd * g.y + bt.y;
    ((float2*)(out + (size_t)row * Dd))[t] = o2;
}

// ---------------- pipelined GEMM body (round-8 verbatim) --------------------
__device__ __forceinline__ void gemm_body(
        const float* __restrict__ A, const float* __restrict__ W,
        const float* __restrict__ bias, float* __restrict__ C,
        int M, int N, int K, int m0, int n0, float* sm) {
    float* As = sm;                             // [128][36]
    float* Bs = sm + 128 * 36;                  // [64][36]
    const int t = threadIdx.x;
    const int warp = t >> 5;
    const int wm = warp & 3, wn = warp >> 2;
    const int lrow = t >> 3, lc = (t & 7) * 4;

    const float* Ap = A + (size_t)(m0 + lrow) * K + lc;
    const float* Wp = W + (size_t)(n0 + lrow) * K + lc;

    float4 av[4], wv[2];
    #pragma unroll
    for (int i = 0; i < 4; i++) av[i] = *(const float4*)(Ap + (size_t)i * 32 * K);
    #pragma unroll
    for (int i = 0; i < 2; i++) wv[i] = *(const float4*)(Wp + (size_t)i * 32 * K);

    wmma::fragment<wmma::accumulator, 16, 16, 8, float> acc[2][2];
    #pragma unroll
    for (int i = 0; i < 2; i++)
        #pragma unroll
        for (int j = 0; j < 2; j++) wmma::fill_fragment(acc[i][j], 0.0f);

    for (int k0 = 0; k0 < K; k0 += 32) {
        #pragma unroll
        for (int i = 0; i < 4; i++) {
            float* d = &As[(i * 32 + lrow) * 36 + lc];
            d[0] = f2t(av[i].x); d[1] = f2t(av[i].y);
            d[2] = f2t(av[i].z); d[3] = f2t(av[i].w);
        }
        #pragma unroll
        for (int i = 0; i < 2; i++) {
            float* d = &Bs[(i * 32 + lrow) * 36 + lc];
            d[0] = f2t(wv[i].x); d[1] = f2t(wv[i].y);
            d[2] = f2t(wv[i].z); d[3] = f2t(wv[i].w);
        }
        __syncthreads();
        if (k0 + 32 < K) {
            #pragma unroll
            for (int i = 0; i < 4; i++)
                av[i] = *(const float4*)(Ap + (size_t)i * 32 * K + k0 + 32);
            #pragma unroll
            for (int i = 0; i < 2; i++)
                wv[i] = *(const float4*)(Wp + (size_t)i * 32 * K + k0 + 32);
        }
        #pragma unroll
        for (int kk = 0; kk < 4; kk++) {
            wmma::fragment<wmma::matrix_a, 16, 16, 8, wmma::precision::tf32, wmma::row_major> a[2];
            wmma::fragment<wmma::matrix_b, 16, 16, 8, wmma::precision::tf32, wmma::col_major> b[2];
            wmma::load_matrix_sync(a[0], &As[(wm * 32) * 36 + kk * 8], 36);
            wmma::load_matrix_sync(a[1], &As[(wm * 32 + 16) * 36 + kk * 8], 36);
            wmma::load_matrix_sync(b[0], &Bs[(wn * 32) * 36 + kk * 8], 36);
            wmma::load_matrix_sync(b[1], &Bs[(wn * 32 + 16) * 36 + kk * 8], 36);
            #pragma unroll
            for (int i = 0; i < 2; i++)
                #pragma unroll
                for (int j = 0; j < 2; j++)
                    wmma::mma_sync(acc[i][j], a[i], b[j], acc[i][j]);
        }
        __syncthreads();
    }
    #pragma unroll
    for (int i = 0; i < 2; i++)
        #pragma unroll
        for (int j = 0; j < 2; j++)
            wmma::store_matrix_sync(&sm[(wm * 32 + i * 16) * 68 + wn * 32 + j * 16],
                                    acc[i][j], 68, wmma::mem_row_major);
    __syncthreads();
    #pragma unroll
    for (int i = 0; i < 8; i++) {
        int idx = i * 256 + t, row = idx >> 4, c = (idx & 15) * 4;
        float4 o;
        float b0 = 0.f, b1 = 0.f, b2 = 0.f, b3 = 0.f;
        if (bias) { b0 = bias[n0+c]; b1 = bias[n0+c+1]; b2 = bias[n0+c+2]; b3 = bias[n0+c+3]; }
        o.x = sm[row * 68 + c]     + b0;
        o.y = sm[row * 68 + c + 1] + b1;
        o.z = sm[row * 68 + c + 2] + b2;
        o.w = sm[row * 68 + c + 3] + b3;
        *(float4*)(C + (size_t)(m0 + row) * N + n0 + c) = o;
    }
}

__global__ void __launch_bounds__(256, 2) gemm_nt_wmma(
        const float* __restrict__ A, const float* __restrict__ W,
        const float* __restrict__ bias, float* __restrict__ C,
        int M, int N, int K) {
    __shared__ float sm[128 * 68];
    gemm_body(A, W, bias, C, M, N, K, blockIdx.y * 128, blockIdx.x * 64, sm);
}

__global__ void __launch_bounds__(256, 2) gemm_qkv_wmma(
        const float* __restrict__ A,
        const float* __restrict__ W0, const float* __restrict__ W1, const float* __restrict__ W2,
        const float* __restrict__ b0, const float* __restrict__ b1, const float* __restrict__ b2,
        float* __restrict__ C0, float* __restrict__ C1, float* __restrict__ C2) {
    __shared__ float sm[128 * 68];
    const int z = blockIdx.z;
    const float* W = (z == 0) ? W0 : (z == 1) ? W1 : W2;
    const float* bb = (z == 0) ? b0 : (z == 1) ? b1 : b2;
    float* C = (z == 0) ? C0 : (z == 1) ? C1 : C2;
    gemm_body(A, W, bb, C, 8192, 512, 512, blockIdx.y * 128, blockIdx.x * 64, sm);
}

// ---------------- TF32 wmma QK^T, plain store (round-8 verbatim) ------------
// Used for position scores (x_batched = 0).
__global__ void __launch_bounds__(256, 2) qk_wmma(
        const float* __restrict__ q, const float* __restrict__ X, int x_batched,
        const float* __restrict__ hbias, float* __restrict__ out) {
    __shared__ float sm[2 * 128 * 36];
    float* Qs = sm;
    float* Ks = sm + 128 * 36;
    const int t = threadIdx.x;
    const int warp = t >> 5;
    const int wm = warp & 1, wn = warp >> 1;
    const int bh = blockIdx.z, b = bh >> 3, h = bh & 7;
    const int s0 = blockIdx.y * 128, t0 = blockIdx.x * 128;
    const float* Xb = X + (x_batched ? (size_t)b * Ss * Dd : 0);
    const int lrow = t >> 3, lc = (t & 7) * 4;

    const float* Qp = q  + (size_t)(b * Ss + s0 + lrow) * Dd + h * 64 + lc;
    const float* Kp = Xb + (size_t)(t0 + lrow) * Dd + h * 64 + lc;

    float4 qv[4], kv[4];
    #pragma unroll
    for (int i = 0; i < 4; i++) {
        qv[i] = *(const float4*)(Qp + (size_t)i * 32 * Dd);
        kv[i] = *(const float4*)(Kp + (size_t)i * 32 * Dd);
    }

    wmma::fragment<wmma::accumulator, 16, 16, 8, float> acc[4][2];
    #pragma unroll
    for (int i = 0; i < 4; i++)
        #pragma unroll
        for (int j = 0; j < 2; j++) wmma::fill_fragment(acc[i][j], 0.0f);

    #pragma unroll
    for (int kc = 0; kc < 2; kc++) {
        const float* bb = &hbias[h * 64 + kc * 32 + lc];
        float bb0 = bb[0], bb1 = bb[1], bb2 = bb[2], bb3 = bb[3];
        #pragma unroll
        for (int i = 0; i < 4; i++) {
            float* d = &Qs[(i * 32 + lrow) * 36 + lc];
            d[0] = f2t(qv[i].x + bb0); d[1] = f2t(qv[i].y + bb1);
            d[2] = f2t(qv[i].z + bb2); d[3] = f2t(qv[i].w + bb3);
            float* e = &Ks[(i * 32 + lrow) * 36 + lc];
            e[0] = f2t(kv[i].x); e[1] = f2t(kv[i].y);
            e[2] = f2t(kv[i].z); e[3] = f2t(kv[i].w);
        }
        __syncthreads();
        if (kc == 0) {
            #pragma unroll
            for (int i = 0; i < 4; i++) {
                qv[i] = *(const float4*)(Qp + (size_t)i * 32 * Dd + 32);
                kv[i] = *(const float4*)(Kp + (size_t)i * 32 * Dd + 32);
            }
        }
        #pragma unroll
        for (int kk = 0; kk < 4; kk++) {
            wmma::fragment<wmma::matrix_a, 16, 16, 8, wmma::precision::tf32, wmma::row_major> a[4];
            wmma::fragment<wmma::matrix_b, 16, 16, 8, wmma::precision::tf32, wmma::col_major> bf[2];
            #pragma unroll
            for (int i = 0; i < 4; i++)
                wmma::load_matrix_sync(a[i], &Qs[(wm * 64 + i * 16) * 36 + kk * 8], 36);
            #pragma unroll
            for (int j = 0; j < 2; j++)
                wmma::load_matrix_sync(bf[j], &Ks[(wn * 32 + j * 16) * 36 + kk * 8], 36);
            #pragma unroll
            for (int i = 0; i < 4; i++)
                #pragma unroll
                for (int j = 0; j < 2; j++)
                    wmma::mma_sync(acc[i][j], a[i], bf[j], acc[i][j]);
        }
        __syncthreads();
    }
    #pragma unroll
    for (int i = 0; i < 4; i++)
        #pragma unroll
        for (int j = 0; j < 2; j++)
            wmma::store_matrix_sync(
                out + ((size_t)bh * Ss + s0 + wm * 64 + i * 16) * Ss + t0 + wn * 32 + j * 16,
                acc[i][j], Ss, wmma::mem_row_major);
}

// ---------------- content QK^T + fused exp/shift epilogue -------------------
// Round-8 mainloop + ROUND-5 epilogue (validated passing in round 5).
__global__ void __launch_bounds__(256, 2) qk_content_wmma(
        const float* __restrict__ q, const float* __restrict__ k,
        const float* __restrict__ ubias, const float* __restrict__ ps,
        float* __restrict__ P, float* __restrict__ lpart) {
    __shared__ float sm[2 * 128 * 36];
    float* Qs = sm;
    float* Ks = sm + 128 * 36;
    const int t = threadIdx.x;
    const int warp = t >> 5;
    const int wm = warp & 1, wn = warp >> 1;
    const int bh = blockIdx.z, b = bh >> 3, h = bh & 7;
    const int s0 = blockIdx.y * 128, t0 = blockIdx.x * 128;
    const int lrow = t >> 3, lc = (t & 7) * 4;
    const float scale = 0.04419417382415922f;

    const float* Qp = q + (size_t)(b * Ss + s0 + lrow) * Dd + h * 64 + lc;
    const float* Kp = k + (size_t)(b * Ss + t0 + lrow) * Dd + h * 64 + lc;

    float4 qv[4], kv[4];
    #pragma unroll
    for (int i = 0; i < 4; i++) {
        qv[i] = *(const float4*)(Qp + (size_t)i * 32 * Dd);
        kv[i] = *(const float4*)(Kp + (size_t)i * 32 * Dd);
    }

    wmma::fragment<wmma::accumulator, 16, 16, 8, float> acc[4][2];
    #pragma unroll
    for (int i = 0; i < 4; i++)
        #pragma unroll
        for (int j = 0; j < 2; j++) wmma::fill_fragment(acc[i][j], 0.0f);

    #pragma unroll
    for (int kc = 0; kc < 2; kc++) {
        const float* bb = &ubias[h * 64 + kc * 32 + lc];
        float bb0 = bb[0], bb1 = bb[1], bb2 = bb[2], bb3 = bb[3];
        #pragma unroll
        for (int i = 0; i < 4; i++) {
            float* d = &Qs[(i * 32 + lrow) * 36 + lc];
            d[0] = f2t(qv[i].x + bb0); d[1] = f2t(qv[i].y + bb1);
            d[2] = f2t(qv[i].z + bb2); d[3] = f2t(qv[i].w + bb3);
            float* e = &Ks[(i * 32 + lrow) * 36 + lc];
            e[0] = f2t(kv[i].x); e[1] = f2t(kv[i].y);
            e[2] = f2t(kv[i].z); e[3] = f2t(kv[i].w);
        }
        __syncthreads();
        if (kc == 0) {
            #pragma unroll
            for (int i = 0; i < 4; i++) {
                qv[i] = *(const float4*)(Qp + (size_t)i * 32 * Dd + 32);
                kv[i] = *(const float4*)(Kp + (size_t)i * 32 * Dd + 32);
            }
        }
        #pragma unroll
        for (int kk = 0; kk < 4; kk++) {
            wmma::fragment<wmma::matrix_a, 16, 16, 8, wmma::precision::tf32, wmma::row_major> a[4];
            wmma::fragment<wmma::matrix_b, 16, 16, 8, wmma::precision::tf32, wmma::col_major> bf[2];
            #pragma unroll
            for (int i = 0; i < 4; i++)
                wmma::load_matrix_sync(a[i], &Qs[(wm * 64 + i * 16) * 36 + kk * 8], 36);
            #pragma unroll
            for (int j = 0; j < 2; j++)
                wmma::load_matrix_sync(bf[j], &Ks[(wn * 32 + j * 16) * 36 + kk * 8], 36);
            #pragma unroll
            for (int i = 0; i < 4; i++)
                #pragma unroll
                for (int j = 0; j < 2; j++)
                    wmma::mma_sync(acc[i][j], a[i], bf[j], acc[i][j]);
        }
        __syncthreads();
    }

    // ---- round-5 epilogue (verbatim): two 64-col waves through stage -------
    float* stage = sm;                          // 128*68 = 8704 <= 9216 floats
    const int r2 = t >> 1, half = t & 1;
    const int s = s0 + r2;
    const float* p0 = ps + ((size_t)bh * Ss + s) * Ss;
    const float* p1 = p0 + Ss;
    float sum = 0.0f;
    #pragma unroll
    for (int wave = 0; wave < 2; wave++) {
        if ((wn >> 1) == wave) {
            #pragma unroll
            for (int i = 0; i < 4; i++)
                #pragma unroll
                for (int j = 0; j < 2; j++)
                    wmma::store_matrix_sync(
                        &stage[(wm * 64 + i * 16) * 68 + (wn & 1) * 32 + j * 16],
                        acc[i][j], 68, wmma::mem_row_major);
        }
        __syncthreads();
        const int cbase = half * 32;
        const int tt0 = t0 + wave * 64 + cbase;
        float* prow = P + ((size_t)bh * Ss + s) * Ss + tt0;
        #pragma unroll
        for (int j4 = 0; j4 < 8; j4++) {
            float4 o;
            float* op = (float*)&o;
            #pragma unroll
            for (int u = 0; u < 4; u++) {
                int tt = tt0 + j4 * 4 + u;
                float p;
                if (tt <= s)          p = p0[Ss - 1 - s + tt];
                else if (tt == s + 1) p = 0.0f;
                else                  p = p1[tt - s - 2];
                float e = __expf((stage[r2 * 68 + cbase + j4 * 4 + u] + p) * scale);
                op[u] = e;
                sum += e;
            }
            *(float4*)(prow + j4 * 4) = o;
        }
        __syncthreads();
    }
    sum += __shfl_xor_sync(0xffffffffu, sum, 1);
    if (half == 0)
        lpart[((size_t)bh * Ss + s) * 16 + blockIdx.x] = sum;
}

// ---------------- ctx = (P * 1/l) @ v per (b,h) -----------------------------
// Round-8 pipelined mainloop; linv computed inline from lpart.
__global__ void __launch_bounds__(256, 2) ctx_wmma(
        const float* __restrict__ P, const float* __restrict__ v,
        const float* __restrict__ lpart, float* __restrict__ ctx) {
    __shared__ float smbuf[128 * 36 + 32 * 68];
    __shared__ float linv_s[128];
    float* As = smbuf;               // [128][36]
    float* Bs = smbuf + 128 * 36;    // [32][68]
    const int t = threadIdx.x;
    const int warp = t >> 5;
    const int wm = warp & 3, wn = warp >> 2;
    const int bh = blockIdx.z, b = bh >> 3, h = bh & 7;
    const int s0 = blockIdx.y * 128;

    if (t < 128) {
        const float* lp = lpart + ((size_t)bh * Ss + s0 + t) * 16;
        float l = 0.0f;
        #pragma unroll
        for (int i = 0; i < 16; i++) l += lp[i];
        linv_s[t] = 1.0f / l;
    }
    __syncthreads();

    const int lrow = t >> 3, lc = (t & 7) * 4;
    const int vrow = t >> 4, vc = (t & 15) * 4;
    const float* Ap = P + ((size_t)bh * Ss + s0 + lrow) * Ss + lc;
    const float* Vp = v + ((size_t)(b * Ss + vrow)) * Dd + h * 64 + vc;

    float li[4];
    #pragma unroll
    for (int i = 0; i < 4; i++) li[i] = linv_s[i * 32 + lrow];

    float4 av[4], vv[2];
    #pragma unroll
    for (int i = 0; i < 4; i++) av[i] = *(const float4*)(Ap + (size_t)i * 32 * Ss);
    #pragma unroll
    for (int i = 0; i < 2; i++) vv[i] = *(const float4*)(Vp + (size_t)i * 16 * Dd);

    wmma::fragment<wmma::accumulator, 16, 16, 8, float> acc[2][2];
    #pragma unroll
    for (int i = 0; i < 2; i++)
        #pragma unroll
        for (int j = 0; j < 2; j++) wmma::fill_fragment(acc[i][j], 0.0f);

    for (int k0 = 0; k0 < Ss; k0 += 32) {
        #pragma unroll
        for (int i = 0; i < 4; i++) {
            float* d = &As[(i * 32 + lrow) * 36 + lc];
            d[0] = f2t(av[i].x * li[i]); d[1] = f2t(av[i].y * li[i]);
            d[2] = f2t(av[i].z * li[i]); d[3] = f2t(av[i].w * li[i]);
        }
        #pragma unroll
        for (int i = 0; i < 2; i++) {
            float* e = &Bs[(i * 16 + vrow) * 68 + vc];
            e[0] = f2t(vv[i].x); e[1] = f2t(vv[i].y);
            e[2] = f2t(vv[i].z); e[3] = f2t(vv[i].w);
        }
        __syncthreads();
        if (k0 + 32 < Ss) {
            #pragma unroll
            for (int i = 0; i < 4; i++)
                av[i] = *(const float4*)(Ap + (size_t)i * 32 * Ss + k0 + 32);
            #pragma unroll
            for (int i = 0; i < 2; i++)
                vv[i] = *(const float4*)(Vp + (size_t)(i * 16 + k0 + 32) * Dd);
        }
        #pragma unroll
        for (int kk = 0; kk < 4; kk++) {
            wmma::fragment<wmma::matrix_a, 16, 16, 8, wmma::precision::tf32, wmma::row_major> a[2];
            wmma::fragment<wmma::matrix_b, 16, 16, 8, wmma::precision::tf32, wmma::row_major> bf[2];
            #pragma unroll
            for (int i = 0; i < 2; i++)
                wmma::load_matrix_sync(a[i], &As[(wm * 32 + i * 16) * 36 + kk * 8], 36);
            #pragma unroll
            for (int j = 0; j < 2; j++)
                wmma::load_matrix_sync(bf[j], &Bs[(kk * 8) * 68 + wn * 32 + j * 16], 68);
            #pragma unroll
            for (int i = 0; i < 2; i++)
                #pragma unroll
                for (int j = 0; j < 2; j++)
                    wmma::mma_sync(acc[i][j], a[i], bf[j], acc[i][j]);
        }
        __syncthreads();
    }
    #pragma unroll
    for (int i = 0; i < 2; i++)
        #pragma unroll
        for (int j = 0; j < 2; j++)
            wmma::store_matrix_sync(
                ctx + (size_t)(b * Ss + s0 + wm * 32 + i * 16) * Dd + h * 64 + wn * 32 + j * 16,
                acc[i][j], Dd, wmma::mem_row_major);
}

// ---------------- launch -----------------------------------------------------
extern "C" void kernel_launch(void* const* d_in, const int* in_sizes, int n_in,
                              void* d_out, int out_size) {
    const float* inputs = (const float*)d_in[0];
    const float* gamma  = (const float*)d_in[1];
    const float* beta   = (const float*)d_in[2];
    const float* Wq     = (const float*)d_in[3];
    const float* bq     = (const float*)d_in[4];
    const float* Wk     = (const float*)d_in[5];
    const float* bk     = (const float*)d_in[6];
    const float* Wv     = (const float*)d_in[7];
    const float* bv     = (const float*)d_in[8];
    const float* Wpos   = (const float*)d_in[9];
    const float* ub     = (const float*)d_in[10];
    const float* vb     = (const float*)d_in[11];
    const float* Wo     = (const float*)d_in[12];
    const float* bo     = (const float*)d_in[13];
    float* out = (float*)d_out;

    float *xn, *q, *k, *v, *ctx, *pe, *pos, *ps, *P, *lp;
    cudaGetSymbolAddress((void**)&xn,  g_xn);
    cudaGetSymbolAddress((void**)&q,   g_q);
    cudaGetSymbolAddress((void**)&k,   g_k);
    cudaGetSymbolAddress((void**)&v,   g_v);
    cudaGetSymbolAddress((void**)&ctx, g_ctx);
    cudaGetSymbolAddress((void**)&pe,  g_pe);
    cudaGetSymbolAddress((void**)&pos, g_pos);
    cudaGetSymbolAddress((void**)&ps,  g_ps);
    cudaGetSymbolAddress((void**)&P,   g_p);
    cudaGetSymbolAddress((void**)&lp,  g_lp);

    pe_kernel<<<2048, 256>>>(pe);
    ln_kernel<<<Bb * Ss, 256>>>(inputs, gamma, beta, xn);

    gemm_qkv_wmma<<<dim3(8, 64, 3), 256>>>(xn, Wq, Wk, Wv, bq, bk, bv, q, k, v);
    gemm_nt_wmma<<<dim3(8, 16), 256>>>(pe, Wpos, nullptr, pos, 2048, 512, 512);

    qk_wmma<<<dim3(16, 16, 32), 256>>>(q, pos, 0, vb, ps);             // raw PS first
    qk_content_wmma<<<dim3(16, 16, 32), 256>>>(q, k, ub, ps, P, lp);   // fused exp

    ctx_wmma<<<dim3(1, 16, 32), 256>>>(P, v, lp, ctx);
    gemm_nt_wmma<<<dim3(8, 64), 256>>>(ctx, Wo, bo, out, 8192, 512, 512);
}

// round 12
// speedup vs baseline: 1.3036x; 1.3036x over previous
#include <cuda_runtime.h>
#include <mma.h>
#include <math.h>
using namespace nvcuda;

#define Bb 4
#define Ss 2048
#define Dd 512
#define Hh 8

// ---------------- scratch ---------------------------------------------------
__device__ float g_xn [Bb*Ss*Dd];
__device__ float g_q  [Bb*Ss*Dd];
__device__ float g_k  [Bb*Ss*Dd];
__device__ float g_v  [Bb*Ss*Dd];
__device__ float g_ctx[Bb*Ss*Dd];
__device__ float g_pe [Ss*Dd];
__device__ float g_pos[Ss*Dd];
__device__ float g_ps [(size_t)Bb*Hh*Ss*Ss];   // raw position scores
__device__ float g_sc [(size_t)Bb*Hh*Ss*Ss];   // content scores -> attn probs

__device__ __forceinline__ float f2t(float x) {
    unsigned r; asm("cvt.rna.tf32.f32 %0, %1;" : "=r"(r) : "f"(x));
    return __uint_as_float(r);
}

// ---------------- sinusoidal positional encoding ---------------------------
__global__ void pe_kernel(float* __restrict__ pe) {
    int idx = blockIdx.x * blockDim.x + threadIdx.x;
    int s = idx >> 8;
    int i = idx & 255;
    float div = expf((2.0f * (float)i) * (-9.210340371976184f / 512.0f));
    float a = (float)s * div;
    pe[s * Dd + 2 * i]     = sinf(a);
    pe[s * Dd + 2 * i + 1] = cosf(a);
}

// ---------------- layernorm -------------------------------------------------
__global__ void ln_kernel(const float* __restrict__ x,
                          const float* __restrict__ gamma,
                          const float* __restrict__ beta,
                          float* __restrict__ out) {
    int row = blockIdx.x;
    const float2* xr = (const float2*)(x + (size_t)row * Dd);
    int t = threadIdx.x;
    float2 v = xr[t];
    float s1 = v.x + v.y;
    float s2 = v.x * v.x + v.y * v.y;
    #pragma unroll
    for (int o = 16; o; o >>= 1) {
        s1 += __shfl_xor_sync(0xffffffffu, s1, o);
        s2 += __shfl_xor_sync(0xffffffffu, s2, o);
    }
    __shared__ float r1[8], r2[8];
    if ((t & 31) == 0) { r1[t >> 5] = s1; r2[t >> 5] = s2; }
    __syncthreads();
    float S1 = 0.f, S2 = 0.f;
    #pragma unroll
    for (int i = 0; i < 8; i++) { S1 += r1[i]; S2 += r2[i]; }
    float mean = S1 * (1.0f / 512.0f);
    float var  = S2 * (1.0f / 512.0f) - mean * mean;
    float rstd = rsqrtf(var + 1e-5f);
    float2 g  = ((const float2*)gamma)[t];
    float2 bt = ((const float2*)beta)[t];
    float2 o2;
    o2.x = (v.x - mean) * rstd * g.x + bt.x;
    o2.y = (v.y - mean) * rstd * g.y + bt.y;
    ((float2*)(out + (size_t)row * Dd))[t] = o2;
}

// ---------------- double-buffered pipelined GEMM body -----------------------
// smem layout: buf0 [128*36 A | 64*36 B], buf1 same => 13824 floats.
// Epilogue reuses sm as [128][68] stage (8704 floats).
__device__ __forceinline__ void gemm_body(
        const float* __restrict__ A, const float* __restrict__ W,
        const float* __restrict__ bias, float* __restrict__ C,
        int M, int N, int K, int m0, int n0, float* sm) {
    const int t = threadIdx.x;
    const int warp = t >> 5;
    const int wm = warp & 3, wn = warp >> 2;
    const int lrow = t >> 3, lc = (t & 7) * 4;

    const float* Ap = A + (size_t)(m0 + lrow) * K + lc;
    const float* Wp = W + (size_t)(n0 + lrow) * K + lc;

    float4 av[4], wv[2];
    #pragma unroll
    for (int i = 0; i < 4; i++) av[i] = *(const float4*)(Ap + (size_t)i * 32 * K);
    #pragma unroll
    for (int i = 0; i < 2; i++) wv[i] = *(const float4*)(Wp + (size_t)i * 32 * K);

    wmma::fragment<wmma::accumulator, 16, 16, 8, float> acc[2][2];
    #pragma unroll
    for (int i = 0; i < 2; i++)
        #pragma unroll
        for (int j = 0; j < 2; j++) wmma::fill_fragment(acc[i][j], 0.0f);

    int buf = 0;
    for (int k0 = 0; k0 < K; k0 += 32, buf ^= 1) {
        float* As = sm + buf * 6912;
        float* Bs = As + 128 * 36;
        #pragma unroll
        for (int i = 0; i < 4; i++) {
            float* d = &As[(i * 32 + lrow) * 36 + lc];
            d[0] = f2t(av[i].x); d[1] = f2t(av[i].y);
            d[2] = f2t(av[i].z); d[3] = f2t(av[i].w);
        }
        #pragma unroll
        for (int i = 0; i < 2; i++) {
            float* d = &Bs[(i * 32 + lrow) * 36 + lc];
            d[0] = f2t(wv[i].x); d[1] = f2t(wv[i].y);
            d[2] = f2t(wv[i].z); d[3] = f2t(wv[i].w);
        }
        __syncthreads();
        if (k0 + 32 < K) {
            #pragma unroll
            for (int i = 0; i < 4; i++)
                av[i] = *(const float4*)(Ap + (size_t)i * 32 * K + k0 + 32);
            #pragma unroll
            for (int i = 0; i < 2; i++)
                wv[i] = *(const float4*)(Wp + (size_t)i * 32 * K + k0 + 32);
        }
        #pragma unroll
        for (int kk = 0; kk < 4; kk++) {
            wmma::fragment<wmma::matrix_a, 16, 16, 8, wmma::precision::tf32, wmma::row_major> a[2];
            wmma::fragment<wmma::matrix_b, 16, 16, 8, wmma::precision::tf32, wmma::col_major> b[2];
            wmma::load_matrix_sync(a[0], &As[(wm * 32) * 36 + kk * 8], 36);
            wmma::load_matrix_sync(a[1], &As[(wm * 32 + 16) * 36 + kk * 8], 36);
            wmma::load_matrix_sync(b[0], &Bs[(wn * 32) * 36 + kk * 8], 36);
            wmma::load_matrix_sync(b[1], &Bs[(wn * 32 + 16) * 36 + kk * 8], 36);
            #pragma unroll
            for (int i = 0; i < 2; i++)
                #pragma unroll
                for (int j = 0; j < 2; j++)
                    wmma::mma_sync(acc[i][j], a[i], b[j], acc[i][j]);
        }
        // no trailing sync: next iter writes the other buffer; its barrier
        // separates this iter's reads from the overwrite two iters later.
    }
    __syncthreads();   // all MMA reads done before stage reuse
    #pragma unroll
    for (int i = 0; i < 2; i++)
        #pragma unroll
        for (int j = 0; j < 2; j++)
            wmma::store_matrix_sync(&sm[(wm * 32 + i * 16) * 68 + wn * 32 + j * 16],
                                    acc[i][j], 68, wmma::mem_row_major);
    __syncthreads();
    #pragma unroll
    for (int i = 0; i < 8; i++) {
        int idx = i * 256 + t, row = idx >> 4, c = (idx & 15) * 4;
        float4 o;
        float b0 = 0.f, b1 = 0.f, b2 = 0.f, b3 = 0.f;
        if (bias) { b0 = bias[n0+c]; b1 = bias[n0+c+1]; b2 = bias[n0+c+2]; b3 = bias[n0+c+3]; }
        o.x = sm[row * 68 + c]     + b0;
        o.y = sm[row * 68 + c + 1] + b1;
        o.z = sm[row * 68 + c + 2] + b2;
        o.w = sm[row * 68 + c + 3] + b3;
        *(float4*)(C + (size_t)(m0 + row) * N + n0 + c) = o;
    }
}

__global__ void __launch_bounds__(256, 2) gemm_nt_wmma(
        const float* __restrict__ A, const float* __restrict__ W,
        const float* __restrict__ bias, float* __restrict__ C,
        int M, int N, int K) {
    extern __shared__ float dsm[];
    gemm_body(A, W, bias, C, M, N, K, blockIdx.y * 128, blockIdx.x * 64, dsm);
}

__global__ void __launch_bounds__(256, 2) gemm_qkv_wmma(
        const float* __restrict__ A,
        const float* __restrict__ W0, const float* __restrict__ W1, const float* __restrict__ W2,
        const float* __restrict__ b0, const float* __restrict__ b1, const float* __restrict__ b2,
        float* __restrict__ C0, float* __restrict__ C1, float* __restrict__ C2) {
    extern __shared__ float dsm[];
    const int z = blockIdx.z;
    const float* W = (z == 0) ? W0 : (z == 1) ? W1 : W2;
    const float* bb = (z == 0) ? b0 : (z == 1) ? b1 : b2;
    float* C = (z == 0) ? C0 : (z == 1) ? C1 : C2;
    gemm_body(A, W, bb, C, 8192, 512, 512, blockIdx.y * 128, blockIdx.x * 64, dsm);
}

// ---------------- TF32 wmma QK^T (round-8 + double buffer) ------------------
// smem: chunk0 [Qs 128*36 | Ks 128*36], chunk1 same => 18432 floats.
__global__ void __launch_bounds__(256, 2) qk_wmma(
        const float* __restrict__ q, const float* __restrict__ X, int x_batched,
        const float* __restrict__ hbias, float* __restrict__ out) {
    extern __shared__ float dsm[];
    const int t = threadIdx.x;
    const int warp = t >> 5;
    const int wm = warp & 1, wn = warp >> 1;
    const int bh = blockIdx.z, b = bh >> 3, h = bh & 7;
    const int s0 = blockIdx.y * 128, t0 = blockIdx.x * 128;
    const float* Xb = X + (x_batched ? (size_t)b * Ss * Dd : 0);
    const int lrow = t >> 3, lc = (t & 7) * 4;

    const float* Qp = q  + (size_t)(b * Ss + s0 + lrow) * Dd + h * 64 + lc;
    const float* Kp = Xb + (size_t)(t0 + lrow) * Dd + h * 64 + lc;

    float4 qv[4], kv[4];
    #pragma unroll
    for (int i = 0; i < 4; i++) {
        qv[i] = *(const float4*)(Qp + (size_t)i * 32 * Dd);
        kv[i] = *(const float4*)(Kp + (size_t)i * 32 * Dd);
    }

    wmma::fragment<wmma::accumulator, 16, 16, 8, float> acc[4][2];
    #pragma unroll
    for (int i = 0; i < 4; i++)
        #pragma unroll
        for (int j = 0; j < 2; j++) wmma::fill_fragment(acc[i][j], 0.0f);

    #pragma unroll
    for (int kc = 0; kc < 2; kc++) {
        float* Qs = dsm + kc * 9216;
        float* Ks = Qs + 128 * 36;
        const float* bb = &hbias[h * 64 + kc * 32 + lc];
        float bb0 = bb[0], bb1 = bb[1], bb2 = bb[2], bb3 = bb[3];
        #pragma unroll
        for (int i = 0; i < 4; i++) {
            float* d = &Qs[(i * 32 + lrow) * 36 + lc];
            d[0] = f2t(qv[i].x + bb0); d[1] = f2t(qv[i].y + bb1);
            d[2] = f2t(qv[i].z + bb2); d[3] = f2t(qv[i].w + bb3);
            float* e = &Ks[(i * 32 + lrow) * 36 + lc];
            e[0] = f2t(kv[i].x); e[1] = f2t(kv[i].y);
            e[2] = f2t(kv[i].z); e[3] = f2t(kv[i].w);
        }
        __syncthreads();
        if (kc == 0) {
            #pragma unroll
            for (int i = 0; i < 4; i++) {
                qv[i] = *(const float4*)(Qp + (size_t)i * 32 * Dd + 32);
                kv[i] = *(const float4*)(Kp + (size_t)i * 32 * Dd + 32);
            }
        }
        #pragma unroll
        for (int kk = 0; kk < 4; kk++) {
            wmma::fragment<wmma::matrix_a, 16, 16, 8, wmma::precision::tf32, wmma::row_major> a[4];
            wmma::fragment<wmma::matrix_b, 16, 16, 8, wmma::precision::tf32, wmma::col_major> bf[2];
            #pragma unroll
            for (int i = 0; i < 4; i++)
                wmma::load_matrix_sync(a[i], &Qs[(wm * 64 + i * 16) * 36 + kk * 8], 36);
            #pragma unroll
            for (int j = 0; j < 2; j++)
                wmma::load_matrix_sync(bf[j], &Ks[(wn * 32 + j * 16) * 36 + kk * 8], 36);
            #pragma unroll
            for (int i = 0; i < 4; i++)
                #pragma unroll
                for (int j = 0; j < 2; j++)
                    wmma::mma_sync(acc[i][j], a[i], bf[j], acc[i][j]);
        }
        // no trailing sync: chunk1 writes the other buffer.
    }
    #pragma unroll
    for (int i = 0; i < 4; i++)
        #pragma unroll
        for (int j = 0; j < 2; j++)
            wmma::store_matrix_sync(
                out + ((size_t)bh * Ss + s0 + wm * 64 + i * 16) * Ss + t0 + wn * 32 + j * 16,
                acc[i][j], Ss, wmma::mem_row_major);
}

// ---------------- fused rel_shift + scale + fixed-max softmax (round-8) -----
__global__ void __launch_bounds__(256) softmax_shift(
        float* __restrict__ sc, const float* __restrict__ ps) {
    const size_t row = blockIdx.x;              // bh*S + s
    const int s = (int)(row & (Ss - 1));
    float* base = sc + row * (size_t)Ss;
    const float* p0 = ps + row * (size_t)Ss;
    const float* p1 = p0 + Ss;
    const int t = threadIdx.x;
    const int c0 = t * 8;
    float4 a = *(float4*)(base + c0);
    float4 bql = *(float4*)(base + c0 + 4);
    float vals[8] = {a.x, a.y, a.z, a.w, bql.x, bql.y, bql.z, bql.w};
    const float scale = 0.04419417382415922f;
    float sum = 0.f;
    #pragma unroll
    for (int j = 0; j < 8; j++) {
        int tt = c0 + j;
        float p;
        if (tt <= s)          p = p0[Ss - 1 - s + tt];
        else if (tt == s + 1) p = 0.0f;
        else                  p = p1[tt - s - 2];
        vals[j] = __expf((vals[j] + p) * scale);   // fixed-max: scores are O(0.1)
        sum += vals[j];
    }
    #pragma unroll
    for (int o = 16; o; o >>= 1) sum += __shfl_xor_sync(0xffffffffu, sum, o);
    __shared__ float rs[8];
    if ((t & 31) == 0) rs[t >> 5] = sum;
    __syncthreads();
    float Sm = 0.f;
    #pragma unroll
    for (int i = 0; i < 8; i++) Sm += rs[i];
    float inv = 1.0f / Sm;
    a.x = vals[0]*inv; a.y = vals[1]*inv; a.z = vals[2]*inv; a.w = vals[3]*inv;
    bql.x = vals[4]*inv; bql.y = vals[5]*inv; bql.z = vals[6]*inv; bql.w = vals[7]*inv;
    *(float4*)(base + c0)     = a;
    *(float4*)(base + c0 + 4) = bql;
}

// ---------------- ctx = attn @ v per (b,h) (round-8 + double buffer) --------
// smem: buf0 [As 128*36 | Bs 32*68], buf1 same => 13568 floats.
__global__ void __launch_bounds__(256, 2) ctx_wmma(
        const float* __restrict__ attn, const float* __restrict__ v,
        float* __restrict__ ctx) {
    extern __shared__ float dsm[];
    const int t = threadIdx.x;
    const int warp = t >> 5;
    const int wm = warp & 3, wn = warp >> 2;
    const int bh = blockIdx.z, b = bh >> 3, h = bh & 7;
    const int s0 = blockIdx.y * 128;

    const int lrow = t >> 3, lc = (t & 7) * 4;
    const int vrow = t >> 4, vc = (t & 15) * 4;
    const float* Ap = attn + ((size_t)bh * Ss + s0 + lrow) * Ss + lc;
    const float* Vp = v + ((size_t)(b * Ss + vrow)) * Dd + h * 64 + vc;

    float4 av[4], vv[2];
    #pragma unroll
    for (int i = 0; i < 4; i++) av[i] = *(const float4*)(Ap + (size_t)i * 32 * Ss);
    #pragma unroll
    for (int i = 0; i < 2; i++) vv[i] = *(const float4*)(Vp + (size_t)i * 16 * Dd);

    wmma::fragment<wmma::accumulator, 16, 16, 8, float> acc[2][2];
    #pragma unroll
    for (int i = 0; i < 2; i++)
        #pragma unroll
        for (int j = 0; j < 2; j++) wmma::fill_fragment(acc[i][j], 0.0f);

    int buf = 0;
    for (int k0 = 0; k0 < Ss; k0 += 32, buf ^= 1) {
        float* As = dsm + buf * 6784;
        float* Bs = As + 128 * 36;
        #pragma unroll
        for (int i = 0; i < 4; i++) {
            float* d = &As[(i * 32 + lrow) * 36 + lc];
            d[0] = f2t(av[i].x); d[1] = f2t(av[i].y);
            d[2] = f2t(av[i].z); d[3] = f2t(av[i].w);
        }
        #pragma unroll
        for (int i = 0; i < 2; i++) {
            float* e = &Bs[(i * 16 + vrow) * 68 + vc];
            e[0] = f2t(vv[i].x); e[1] = f2t(vv[i].y);
            e[2] = f2t(vv[i].z); e[3] = f2t(vv[i].w);
        }
        __syncthreads();
        if (k0 + 32 < Ss) {
            #pragma unroll
            for (int i = 0; i < 4; i++)
                av[i] = *(const float4*)(Ap + (size_t)i * 32 * Ss + k0 + 32);
            #pragma unroll
            for (int i = 0; i < 2; i++)
                vv[i] = *(const float4*)(Vp + (size_t)(i * 16 + k0 + 32) * Dd);
        }
        #pragma unroll
        for (int kk = 0; kk < 4; kk++) {
            wmma::fragment<wmma::matrix_a, 16, 16, 8, wmma::precision::tf32, wmma::row_major> a[2];
            wmma::fragment<wmma::matrix_b, 16, 16, 8, wmma::precision::tf32, wmma::row_major> bf[2];
            #pragma unroll
            for (int i = 0; i < 2; i++)
                wmma::load_matrix_sync(a[i], &As[(wm * 32 + i * 16) * 36 + kk * 8], 36);
            #pragma unroll
            for (int j = 0; j < 2; j++)
                wmma::load_matrix_sync(bf[j], &Bs[(kk * 8) * 68 + wn * 32 + j * 16], 68);
            #pragma unroll
            for (int i = 0; i < 2; i++)
                #pragma unroll
                for (int j = 0; j < 2; j++)
                    wmma::mma_sync(acc[i][j], a[i], bf[j], acc[i][j]);
        }
        // no trailing sync: ping-pong buffers.
    }
    #pragma unroll
    for (int i = 0; i < 2; i++)
        #pragma unroll
        for (int j = 0; j < 2; j++)
            wmma::store_matrix_sync(
                ctx + (size_t)(b * Ss + s0 + wm * 32 + i * 16) * Dd + h * 64 + wn * 32 + j * 16,
                acc[i][j], Dd, wmma::mem_row_major);
}

// ---------------- launch -----------------------------------------------------
extern "C" void kernel_launch(void* const* d_in, const int* in_sizes, int n_in,
                              void* d_out, int out_size) {
    const float* inputs = (const float*)d_in[0];
    const float* gamma  = (const float*)d_in[1];
    const float* beta   = (const float*)d_in[2];
    const float* Wq     = (const float*)d_in[3];
    const float* bq     = (const float*)d_in[4];
    const float* Wk     = (const float*)d_in[5];
    const float* bk     = (const float*)d_in[6];
    const float* Wv     = (const float*)d_in[7];
    const float* bv     = (const float*)d_in[8];
    const float* Wpos   = (const float*)d_in[9];
    const float* ub     = (const float*)d_in[10];
    const float* vb     = (const float*)d_in[11];
    const float* Wo     = (const float*)d_in[12];
    const float* bo     = (const float*)d_in[13];
    float* out = (float*)d_out;

    float *xn, *q, *k, *v, *ctx, *pe, *pos, *ps, *sc;
    cudaGetSymbolAddress((void**)&xn,  g_xn);
    cudaGetSymbolAddress((void**)&q,   g_q);
    cudaGetSymbolAddress((void**)&k,   g_k);
    cudaGetSymbolAddress((void**)&v,   g_v);
    cudaGetSymbolAddress((void**)&ctx, g_ctx);
    cudaGetSymbolAddress((void**)&pe,  g_pe);
    cudaGetSymbolAddress((void**)&pos, g_pos);
    cudaGetSymbolAddress((void**)&ps,  g_ps);
    cudaGetSymbolAddress((void**)&sc,  g_sc);

    const int SM_GEMM = 13824 * 4;   // 55296 B
    const int SM_QK   = 18432 * 4;   // 73728 B
    const int SM_CTX  = 13568 * 4;   // 54272 B
    cudaFuncSetAttribute(gemm_nt_wmma,  cudaFuncAttributeMaxDynamicSharedMemorySize, SM_GEMM);
    cudaFuncSetAttribute(gemm_qkv_wmma, cudaFuncAttributeMaxDynamicSharedMemorySize, SM_GEMM);
    cudaFuncSetAttribute(qk_wmma,       cudaFuncAttributeMaxDynamicSharedMemorySize, SM_QK);
    cudaFuncSetAttribute(ctx_wmma,      cudaFuncAttributeMaxDynamicSharedMemorySize, SM_CTX);

    pe_kernel<<<2048, 256>>>(pe);
    ln_kernel<<<Bb * Ss, 256>>>(inputs, gamma, beta, xn);

    gemm_qkv_wmma<<<dim3(8, 64, 3), 256, SM_GEMM>>>(xn, Wq, Wk, Wv, bq, bk, bv, q, k, v);
    gemm_nt_wmma<<<dim3(8, 16), 256, SM_GEMM>>>(pe, Wpos, nullptr, pos, 2048, 512, 512);

    qk_wmma<<<dim3(16, 16, 32), 256, SM_QK>>>(q, k,   1, ub, sc);   // content scores
    qk_wmma<<<dim3(16, 16, 32), 256, SM_QK>>>(q, pos, 0, vb, ps);   // position scores

    softmax_shift<<<Bb * Hh * Ss, 256>>>(sc, ps);                   // shift+scale+softmax

    ctx_wmma<<<dim3(1, 16, 32), 256, SM_CTX>>>(sc, v, ctx);
    gemm_nt_wmma<<<dim3(8, 64), 256, SM_GEMM>>>(ctx, Wo, bo, out, 8192, 512, 512);
}

// round 13
// speedup vs baseline: 1.4566x; 1.1174x over previous
#include <cuda_runtime.h>
#include <mma.h>
#include <math.h>
using namespace nvcuda;

#define Bb 4
#define Ss 2048
#define Dd 512
#define Hh 8

// ---------------- scratch ---------------------------------------------------
__device__ float g_xn [Bb*Ss*Dd];
__device__ float g_q  [Bb*Ss*Dd];
__device__ float g_k  [Bb*Ss*Dd];
__device__ float g_v  [Bb*Ss*Dd];
__device__ float g_ctx[Bb*Ss*Dd];
__device__ float g_pe [Ss*Dd];
__device__ float g_pos[Ss*Dd];
__device__ float g_ps [(size_t)Bb*Hh*Ss*Ss];   // SHIFTED position scores
__device__ float g_sc [(size_t)Bb*Hh*Ss*Ss];   // raw content scores

__device__ __forceinline__ float f2t(float x) {
    unsigned r; asm("cvt.rna.tf32.f32 %0, %1;" : "=r"(r) : "f"(x));
    return __uint_as_float(r);
}

// ---------------- sinusoidal positional encoding ---------------------------
__global__ void pe_kernel(float* __restrict__ pe) {
    int idx = blockIdx.x * blockDim.x + threadIdx.x;
    int s = idx >> 8;
    int i = idx & 255;
    float div = expf((2.0f * (float)i) * (-9.210340371976184f / 512.0f));
    float a = (float)s * div;
    pe[s * Dd + 2 * i]     = sinf(a);
    pe[s * Dd + 2 * i + 1] = cosf(a);
}

// ---------------- layernorm -------------------------------------------------
__global__ void ln_kernel(const float* __restrict__ x,
                          const float* __restrict__ gamma,
                          const float* __restrict__ beta,
                          float* __restrict__ out) {
    int row = blockIdx.x;
    const float2* xr = (const float2*)(x + (size_t)row * Dd);
    int t = threadIdx.x;
    float2 v = xr[t];
    float s1 = v.x + v.y;
    float s2 = v.x * v.x + v.y * v.y;
    #pragma unroll
    for (int o = 16; o; o >>= 1) {
        s1 += __shfl_xor_sync(0xffffffffu, s1, o);
        s2 += __shfl_xor_sync(0xffffffffu, s2, o);
    }
    __shared__ float r1[8], r2[8];
    if ((t & 31) == 0) { r1[t >> 5] = s1; r2[t >> 5] = s2; }
    __syncthreads();
    float S1 = 0.f, S2 = 0.f;
    #pragma unroll
    for (int i = 0; i < 8; i++) { S1 += r1[i]; S2 += r2[i]; }
    float mean = S1 * (1.0f / 512.0f);
    float var  = S2 * (1.0f / 512.0f) - mean * mean;
    float rstd = rsqrtf(var + 1e-5f);
    float2 g  = ((const float2*)gamma)[t];
    float2 bt = ((const float2*)beta)[t];
    float2 o2;
    o2.x = (v.x - mean) * rstd * g.x + bt.x;
    o2.y = (v.y - mean) * rstd * g.y + bt.y;
    ((float2*)(out + (size_t)row * Dd))[t] = o2;
}

// ---------------- double-buffered pipelined GEMM body (round-12) ------------
__device__ __forceinline__ void gemm_body(
        const float* __restrict__ A, const float* __restrict__ W,
        const float* __restrict__ bias, float* __restrict__ C,
        int M, int N, int K, int m0, int n0, float* sm) {
    const int t = threadIdx.x;
    const int warp = t >> 5;
    const int wm = warp & 3, wn = warp >> 2;
    const int lrow = t >> 3, lc = (t & 7) * 4;

    const float* Ap = A + (size_t)(m0 + lrow) * K + lc;
    const float* Wp = W + (size_t)(n0 + lrow) * K + lc;

    float4 av[4], wv[2];
    #pragma unroll
    for (int i = 0; i < 4; i++) av[i] = *(const float4*)(Ap + (size_t)i * 32 * K);
    #pragma unroll
    for (int i = 0; i < 2; i++) wv[i] = *(const float4*)(Wp + (size_t)i * 32 * K);

    wmma::fragment<wmma::accumulator, 16, 16, 8, float> acc[2][2];
    #pragma unroll
    for (int i = 0; i < 2; i++)
        #pragma unroll
        for (int j = 0; j < 2; j++) wmma::fill_fragment(acc[i][j], 0.0f);

    int buf = 0;
    for (int k0 = 0; k0 < K; k0 += 32, buf ^= 1) {
        float* As = sm + buf * 6912;
        float* Bs = As + 128 * 36;
        #pragma unroll
        for (int i = 0; i < 4; i++) {
            float* d = &As[(i * 32 + lrow) * 36 + lc];
            d[0] = f2t(av[i].x); d[1] = f2t(av[i].y);
            d[2] = f2t(av[i].z); d[3] = f2t(av[i].w);
        }
        #pragma unroll
        for (int i = 0; i < 2; i++) {
            float* d = &Bs[(i * 32 + lrow) * 36 + lc];
            d[0] = f2t(wv[i].x); d[1] = f2t(wv[i].y);
            d[2] = f2t(wv[i].z); d[3] = f2t(wv[i].w);
        }
        __syncthreads();
        if (k0 + 32 < K) {
            #pragma unroll
            for (int i = 0; i < 4; i++)
                av[i] = *(const float4*)(Ap + (size_t)i * 32 * K + k0 + 32);
            #pragma unroll
            for (int i = 0; i < 2; i++)
                wv[i] = *(const float4*)(Wp + (size_t)i * 32 * K + k0 + 32);
        }
        #pragma unroll
        for (int kk = 0; kk < 4; kk++) {
            wmma::fragment<wmma::matrix_a, 16, 16, 8, wmma::precision::tf32, wmma::row_major> a[2];
            wmma::fragment<wmma::matrix_b, 16, 16, 8, wmma::precision::tf32, wmma::col_major> b[2];
            wmma::load_matrix_sync(a[0], &As[(wm * 32) * 36 + kk * 8], 36);
            wmma::load_matrix_sync(a[1], &As[(wm * 32 + 16) * 36 + kk * 8], 36);
            wmma::load_matrix_sync(b[0], &Bs[(wn * 32) * 36 + kk * 8], 36);
            wmma::load_matrix_sync(b[1], &Bs[(wn * 32 + 16) * 36 + kk * 8], 36);
            #pragma unroll
            for (int i = 0; i < 2; i++)
                #pragma unroll
                for (int j = 0; j < 2; j++)
                    wmma::mma_sync(acc[i][j], a[i], b[j], acc[i][j]);
        }
    }
    __syncthreads();
    #pragma unroll
    for (int i = 0; i < 2; i++)
        #pragma unroll
        for (int j = 0; j < 2; j++)
            wmma::store_matrix_sync(&sm[(wm * 32 + i * 16) * 68 + wn * 32 + j * 16],
                                    acc[i][j], 68, wmma::mem_row_major);
    __syncthreads();
    #pragma unroll
    for (int i = 0; i < 8; i++) {
        int idx = i * 256 + t, row = idx >> 4, c = (idx & 15) * 4;
        float4 o;
        float b0 = 0.f, b1 = 0.f, b2 = 0.f, b3 = 0.f;
        if (bias) { b0 = bias[n0+c]; b1 = bias[n0+c+1]; b2 = bias[n0+c+2]; b3 = bias[n0+c+3]; }
        o.x = sm[row * 68 + c]     + b0;
        o.y = sm[row * 68 + c + 1] + b1;
        o.z = sm[row * 68 + c + 2] + b2;
        o.w = sm[row * 68 + c + 3] + b3;
        *(float4*)(C + (size_t)(m0 + row) * N + n0 + c) = o;
    }
}

__global__ void __launch_bounds__(256, 2) gemm_nt_wmma(
        const float* __restrict__ A, const float* __restrict__ W,
        const float* __restrict__ bias, float* __restrict__ C,
        int M, int N, int K) {
    extern __shared__ float dsm[];
    gemm_body(A, W, bias, C, M, N, K, blockIdx.y * 128, blockIdx.x * 64, dsm);
}

__global__ void __launch_bounds__(256, 2) gemm_qkv_wmma(
        const float* __restrict__ A,
        const float* __restrict__ W0, const float* __restrict__ W1, const float* __restrict__ W2,
        const float* __restrict__ b0, const float* __restrict__ b1, const float* __restrict__ b2,
        float* __restrict__ C0, float* __restrict__ C1, float* __restrict__ C2) {
    extern __shared__ float dsm[];
    const int z = blockIdx.z;
    const float* W = (z == 0) ? W0 : (z == 1) ? W1 : W2;
    const float* bb = (z == 0) ? b0 : (z == 1) ? b1 : b2;
    float* C = (z == 0) ? C0 : (z == 1) ? C1 : C2;
    gemm_body(A, W, bb, C, 8192, 512, 512, blockIdx.y * 128, blockIdx.x * 64, dsm);
}

// ---------------- qk mainloop (round-12 verbatim) ---------------------------
__device__ __forceinline__ void qk_mainloop(
        const float* __restrict__ q, const float* __restrict__ Xb,
        const float* __restrict__ hbias,
        int b, int h, int s0, int t0, float* dsm,
        wmma::fragment<wmma::accumulator, 16, 16, 8, float> (&acc)[4][2]) {
    const int t = threadIdx.x;
    const int warp = t >> 5;
    const int wm = warp & 1, wn = warp >> 1;
    const int lrow = t >> 3, lc = (t & 7) * 4;

    const float* Qp = q  + (size_t)(b * Ss + s0 + lrow) * Dd + h * 64 + lc;
    const float* Kp = Xb + (size_t)(t0 + lrow) * Dd + h * 64 + lc;

    float4 qv[4], kv[4];
    #pragma unroll
    for (int i = 0; i < 4; i++) {
        qv[i] = *(const float4*)(Qp + (size_t)i * 32 * Dd);
        kv[i] = *(const float4*)(Kp + (size_t)i * 32 * Dd);
    }

    #pragma unroll
    for (int i = 0; i < 4; i++)
        #pragma unroll
        for (int j = 0; j < 2; j++) wmma::fill_fragment(acc[i][j], 0.0f);

    #pragma unroll
    for (int kc = 0; kc < 2; kc++) {
        float* Qs = dsm + kc * 9216;
        float* Ks = Qs + 128 * 36;
        const float* bb = &hbias[h * 64 + kc * 32 + lc];
        float bb0 = bb[0], bb1 = bb[1], bb2 = bb[2], bb3 = bb[3];
        #pragma unroll
        for (int i = 0; i < 4; i++) {
            float* d = &Qs[(i * 32 + lrow) * 36 + lc];
            d[0] = f2t(qv[i].x + bb0); d[1] = f2t(qv[i].y + bb1);
            d[2] = f2t(qv[i].z + bb2); d[3] = f2t(qv[i].w + bb3);
            float* e = &Ks[(i * 32 + lrow) * 36 + lc];
            e[0] = f2t(kv[i].x); e[1] = f2t(kv[i].y);
            e[2] = f2t(kv[i].z); e[3] = f2t(kv[i].w);
        }
        __syncthreads();
        if (kc == 0) {
            #pragma unroll
            for (int i = 0; i < 4; i++) {
                qv[i] = *(const float4*)(Qp + (size_t)i * 32 * Dd + 32);
                kv[i] = *(const float4*)(Kp + (size_t)i * 32 * Dd + 32);
            }
        }
        #pragma unroll
        for (int kk = 0; kk < 4; kk++) {
            wmma::fragment<wmma::matrix_a, 16, 16, 8, wmma::precision::tf32, wmma::row_major> a[4];
            wmma::fragment<wmma::matrix_b, 16, 16, 8, wmma::precision::tf32, wmma::col_major> bf[2];
            #pragma unroll
            for (int i = 0; i < 4; i++)
                wmma::load_matrix_sync(a[i], &Qs[(wm * 64 + i * 16) * 36 + kk * 8], 36);
            #pragma unroll
            for (int j = 0; j < 2; j++)
                wmma::load_matrix_sync(bf[j], &Ks[(wn * 32 + j * 16) * 36 + kk * 8], 36);
            #pragma unroll
            for (int i = 0; i < 4; i++)
                #pragma unroll
                for (int j = 0; j < 2; j++)
                    wmma::mma_sync(acc[i][j], a[i], bf[j], acc[i][j]);
        }
    }
}

// ---------------- content QK^T: plain fragment store ------------------------
__global__ void __launch_bounds__(256, 2) qk_content_wmma(
        const float* __restrict__ q, const float* __restrict__ k,
        const float* __restrict__ ubias, float* __restrict__ out) {
    extern __shared__ float dsm[];
    const int t = threadIdx.x;
    const int warp = t >> 5;
    const int wm = warp & 1, wn = warp >> 1;
    const int bh = blockIdx.z, b = bh >> 3, h = bh & 7;
    const int s0 = blockIdx.y * 128, t0 = blockIdx.x * 128;

    wmma::fragment<wmma::accumulator, 16, 16, 8, float> acc[4][2];
    qk_mainloop(q, k + (size_t)b * Ss * Dd, ubias, b, h, s0, t0, dsm, acc);

    #pragma unroll
    for (int i = 0; i < 4; i++)
        #pragma unroll
        for (int j = 0; j < 2; j++)
            wmma::store_matrix_sync(
                out + ((size_t)bh * Ss + s0 + wm * 64 + i * 16) * Ss + t0 + wn * 32 + j * 16,
                acc[i][j], Ss, wmma::mem_row_major);
}

// ---------------- position QK^T with SHIFTED scatter store -------------------
// PS[s,j] -> (s, j+s+1-S) if j >= S-1-s, else (s-1, j+s+1). Bijective; the
// diagonal dest (s, s+1) is never written (zeroed by diag_zero_kernel).
__global__ void __launch_bounds__(256, 2) qk_ps_shift_wmma(
        const float* __restrict__ q, const float* __restrict__ pos,
        const float* __restrict__ vbias, float* __restrict__ out) {
    extern __shared__ float dsm[];
    const int t = threadIdx.x;
    const int warp = t >> 5;
    const int wm = warp & 1, wn = warp >> 1;
    const int bh = blockIdx.z, b = bh >> 3, h = bh & 7;
    const int s0 = blockIdx.y * 128, t0 = blockIdx.x * 128;

    wmma::fragment<wmma::accumulator, 16, 16, 8, float> acc[4][2];
    qk_mainloop(q, pos, vbias, b, h, s0, t0, dsm, acc);

    // stage full 128x128 tile (stride 132 -> 16896 floats <= 18432)
    float* stage = dsm;
    __syncthreads();
    #pragma unroll
    for (int i = 0; i < 4; i++)
        #pragma unroll
        for (int j = 0; j < 2; j++)
            wmma::store_matrix_sync(&stage[(wm * 64 + i * 16) * 132 + wn * 32 + j * 16],
                                    acc[i][j], 132, wmma::mem_row_major);
    __syncthreads();

    // scatter: warp w handles rows w*16..w*16+15; lanes cover contiguous cols
    const int w = warp, ln = t & 31;
    float* obase = out + (size_t)bh * Ss * Ss;
    for (int rr = 0; rr < 16; rr++) {
        int row = w * 16 + rr;
        int s = s0 + row;
        #pragma unroll
        for (int cc = 0; cc < 4; cc++) {
            int c = ln + cc * 32;
            int j = t0 + c;
            float val = stage[row * 132 + c];
            int dr, dc;
            if (j >= Ss - 1 - s) { dr = s;     dc = j + s + 1 - Ss; }
            else                 { dr = s - 1; dc = j + s + 1; }
            if (dr >= 0)
                obase[(size_t)dr * Ss + dc] = val;
        }
    }
}

// ---------------- zero the t = s+1 diagonal of shifted ps -------------------
__global__ void diag_zero_kernel(float* __restrict__ psh) {
    int idx = blockIdx.x * 256 + threadIdx.x;    // bh*S + s
    int s = idx & (Ss - 1);
    if (s < Ss - 1)
        psh[(size_t)idx * Ss + s + 1] = 0.0f;
}

// ---------------- fused ctx: P = exp((sc + psh)*scale) in prefetch shadow ---
// Double-buffered pipeline (round-12 ctx); O normalized by 1/rowsum at write.
__global__ void __launch_bounds__(256, 2) ctx_fused_wmma(
        const float* __restrict__ sc, const float* __restrict__ psh,
        const float* __restrict__ v, float* __restrict__ ctx) {
    extern __shared__ float dsm[];
    __shared__ float linv_s[128];
    const int t = threadIdx.x;
    const int warp = t >> 5;
    const int wm = warp & 3, wn = warp >> 2;
    const int bh = blockIdx.z, b = bh >> 3, h = bh & 7;
    const int s0 = blockIdx.y * 128;
    const float scale = 0.04419417382415922f;

    const int lrow = t >> 3, lc = (t & 7) * 4;
    const int vrow = t >> 4, vc = (t & 15) * 4;
    const float* Ap = sc  + ((size_t)bh * Ss + s0 + lrow) * Ss + lc;
    const float* Pp = psh + ((size_t)bh * Ss + s0 + lrow) * Ss + lc;
    const float* Vp = v + ((size_t)(b * Ss + vrow)) * Dd + h * 64 + vc;

    float4 av[4], pv[4], vv[2];
    #pragma unroll
    for (int i = 0; i < 4; i++) {
        av[i] = *(const float4*)(Ap + (size_t)i * 32 * Ss);
        pv[i] = *(const float4*)(Pp + (size_t)i * 32 * Ss);
    }
    #pragma unroll
    for (int i = 0; i < 2; i++) vv[i] = *(const float4*)(Vp + (size_t)i * 16 * Dd);

    wmma::fragment<wmma::accumulator, 16, 16, 8, float> acc[2][2];
    #pragma unroll
    for (int i = 0; i < 2; i++)
        #pragma unroll
        for (int j = 0; j < 2; j++) wmma::fill_fragment(acc[i][j], 0.0f);

    float sums[4] = {0.f, 0.f, 0.f, 0.f};

    int buf = 0;
    for (int k0 = 0; k0 < Ss; k0 += 32, buf ^= 1) {
        float* As = dsm + buf * 6784;
        float* Bs = As + 128 * 36;
        #pragma unroll
        for (int i = 0; i < 4; i++) {
            float e0 = __expf((av[i].x + pv[i].x) * scale);
            float e1 = __expf((av[i].y + pv[i].y) * scale);
            float e2 = __expf((av[i].z + pv[i].z) * scale);
            float e3 = __expf((av[i].w + pv[i].w) * scale);
            sums[i] += e0 + e1 + e2 + e3;
            float* d = &As[(i * 32 + lrow) * 36 + lc];
            d[0] = f2t(e0); d[1] = f2t(e1); d[2] = f2t(e2); d[3] = f2t(e3);
        }
        #pragma unroll
        for (int i = 0; i < 2; i++) {
            float* e = &Bs[(i * 16 + vrow) * 68 + vc];
            e[0] = f2t(vv[i].x); e[1] = f2t(vv[i].y);
            e[2] = f2t(vv[i].z); e[3] = f2t(vv[i].w);
        }
        __syncthreads();
        if (k0 + 32 < Ss) {
            #pragma unroll
            for (int i = 0; i < 4; i++) {
                av[i] = *(const float4*)(Ap + (size_t)i * 32 * Ss + k0 + 32);
                pv[i] = *(const float4*)(Pp + (size_t)i * 32 * Ss + k0 + 32);
            }
            #pragma unroll
            for (int i = 0; i < 2; i++)
                vv[i] = *(const float4*)(Vp + (size_t)(i * 16 + k0 + 32) * Dd);
        }
        #pragma unroll
        for (int kk = 0; kk < 4; kk++) {
            wmma::fragment<wmma::matrix_a, 16, 16, 8, wmma::precision::tf32, wmma::row_major> a[2];
            wmma::fragment<wmma::matrix_b, 16, 16, 8, wmma::precision::tf32, wmma::row_major> bf[2];
            #pragma unroll
            for (int i = 0; i < 2; i++)
                wmma::load_matrix_sync(a[i], &As[(wm * 32 + i * 16) * 36 + kk * 8], 36);
            #pragma unroll
            for (int j = 0; j < 2; j++)
                wmma::load_matrix_sync(bf[j], &Bs[(kk * 8) * 68 + wn * 32 + j * 16], 68);
            #pragma unroll
            for (int i = 0; i < 2; i++)
                #pragma unroll
                for (int j = 0; j < 2; j++)
                    wmma::mma_sync(acc[i][j], a[i], bf[j], acc[i][j]);
        }
    }

    // full row sums: 8 threads (t&7) share each row
    #pragma unroll
    for (int i = 0; i < 4; i++) {
        sums[i] += __shfl_xor_sync(0xffffffffu, sums[i], 1);
        sums[i] += __shfl_xor_sync(0xffffffffu, sums[i], 2);
        sums[i] += __shfl_xor_sync(0xffffffffu, sums[i], 4);
    }
    __syncthreads();   // all MMA smem reads done before stage reuse
    if ((t & 7) == 0) {
        #pragma unroll
        for (int i = 0; i < 4; i++)
            linv_s[i * 32 + lrow] = 1.0f / sums[i];
    }
    #pragma unroll
    for (int i = 0; i < 2; i++)
        #pragma unroll
        for (int j = 0; j < 2; j++)
            wmma::store_matrix_sync(&dsm[(wm * 32 + i * 16) * 68 + wn * 32 + j * 16],
                                    acc[i][j], 68, wmma::mem_row_major);
    __syncthreads();
    #pragma unroll
    for (int i = 0; i < 2; i++) {
        int idx = i * 256 + t, row = idx >> 4, c = (idx & 15) * 4;
        // 128 rows x 64 cols = 2048 float4 -> wait: 8192 elems = 2048 f4 /256 = 8
    }
    #pragma unroll
    for (int i = 0; i < 8; i++) {
        int idx = i * 256 + t, row = idx >> 4, c = (idx & 15) * 4;
        float li = linv_s[row];
        float4 o;
        o.x = dsm[row * 68 + c]     * li;
        o.y = dsm[row * 68 + c + 1] * li;
        o.z = dsm[row * 68 + c + 2] * li;
        o.w = dsm[row * 68 + c + 3] * li;
        *(float4*)(ctx + (size_t)(b * Ss + s0 + row) * Dd + h * 64 + c) = o;
    }
}

// ---------------- launch -----------------------------------------------------
extern "C" void kernel_launch(void* const* d_in, const int* in_sizes, int n_in,
                              void* d_out, int out_size) {
    const float* inputs = (const float*)d_in[0];
    const float* gamma  = (const float*)d_in[1];
    const float* beta   = (const float*)d_in[2];
    const float* Wq     = (const float*)d_in[3];
    const float* bq     = (const float*)d_in[4];
    const float* Wk     = (const float*)d_in[5];
    const float* bk     = (const float*)d_in[6];
    const float* Wv     = (const float*)d_in[7];
    const float* bv     = (const float*)d_in[8];
    const float* Wpos   = (const float*)d_in[9];
    const float* ub     = (const float*)d_in[10];
    const float* vb     = (const float*)d_in[11];
    const float* Wo     = (const float*)d_in[12];
    const float* bo     = (const float*)d_in[13];
    float* out = (float*)d_out;

    float *xn, *q, *k, *v, *ctx, *pe, *pos, *ps, *sc;
    cudaGetSymbolAddress((void**)&xn,  g_xn);
    cudaGetSymbolAddress((void**)&q,   g_q);
    cudaGetSymbolAddress((void**)&k,   g_k);
    cudaGetSymbolAddress((void**)&v,   g_v);
    cudaGetSymbolAddress((void**)&ctx, g_ctx);
    cudaGetSymbolAddress((void**)&pe,  g_pe);
    cudaGetSymbolAddress((void**)&pos, g_pos);
    cudaGetSymbolAddress((void**)&ps,  g_ps);
    cudaGetSymbolAddress((void**)&sc,  g_sc);

    const int SM_GEMM = 13824 * 4;   // 55296 B
    const int SM_QK   = 18432 * 4;   // 73728 B
    const int SM_CTX  = 13568 * 4;   // 54272 B
    cudaFuncSetAttribute(gemm_nt_wmma,    cudaFuncAttributeMaxDynamicSharedMemorySize, SM_GEMM);
    cudaFuncSetAttribute(gemm_qkv_wmma,   cudaFuncAttributeMaxDynamicSharedMemorySize, SM_GEMM);
    cudaFuncSetAttribute(qk_content_wmma, cudaFuncAttributeMaxDynamicSharedMemorySize, SM_QK);
    cudaFuncSetAttribute(qk_ps_shift_wmma,cudaFuncAttributeMaxDynamicSharedMemorySize, SM_QK);
    cudaFuncSetAttribute(ctx_fused_wmma,  cudaFuncAttributeMaxDynamicSharedMemorySize, SM_CTX);

    pe_kernel<<<2048, 256>>>(pe);
    ln_kernel<<<Bb * Ss, 256>>>(inputs, gamma, beta, xn);

    gemm_qkv_wmma<<<dim3(8, 64, 3), 256, SM_GEMM>>>(xn, Wq, Wk, Wv, bq, bk, bv, q, k, v);
    gemm_nt_wmma<<<dim3(8, 16), 256, SM_GEMM>>>(pe, Wpos, nullptr, pos, 2048, 512, 512);

    qk_content_wmma<<<dim3(16, 16, 32), 256, SM_QK>>>(q, k, ub, sc);
    qk_ps_shift_wmma<<<dim3(16, 16, 32), 256, SM_QK>>>(q, pos, vb, ps);
    diag_zero_kernel<<<Bb * Hh * Ss / 256, 256>>>(ps);

    ctx_fused_wmma<<<dim3(1, 16, 32), 256, SM_CTX>>>(sc, ps, v, ctx);
    gemm_nt_wmma<<<dim3(8, 64), 256, SM_GEMM>>>(ctx, Wo, bo, out, 8192, 512, 512);
}

// round 15
// speedup vs baseline: 1.4754x; 1.0129x over previous
#include <cuda_runtime.h>
#include <mma.h>
#include <math.h>
using namespace nvcuda;

#define Bb 4
#define Ss 2048
#define Dd 512
#define Hh 8

// ---------------- scratch ---------------------------------------------------
__device__ float g_xn [Bb*Ss*Dd];
__device__ float g_q  [Bb*Ss*Dd];
__device__ float g_k  [Bb*Ss*Dd];
__device__ float g_v  [Bb*Ss*Dd];
__device__ float g_ctx[Bb*Ss*Dd];
__device__ float g_pe [Ss*Dd];
__device__ float g_pos[Ss*Dd];
__device__ float g_ps [(size_t)Bb*Hh*Ss*Ss];   // SHIFTED position scores
__device__ float g_sc [(size_t)Bb*Hh*Ss*Ss];   // raw content scores

__device__ __forceinline__ float f2t(float x) {
    unsigned r; asm("cvt.rna.tf32.f32 %0, %1;" : "=r"(r) : "f"(x));
    return __uint_as_float(r);
}

// ---------------- sinusoidal positional encoding ---------------------------
__global__ void pe_kernel(float* __restrict__ pe) {
    int idx = blockIdx.x * blockDim.x + threadIdx.x;
    int s = idx >> 8;
    int i = idx & 255;
    float div = expf((2.0f * (float)i) * (-9.210340371976184f / 512.0f));
    float a = (float)s * div;
    pe[s * Dd + 2 * i]     = sinf(a);
    pe[s * Dd + 2 * i + 1] = cosf(a);
}

// ---------------- layernorm -------------------------------------------------
__global__ void ln_kernel(const float* __restrict__ x,
                          const float* __restrict__ gamma,
                          const float* __restrict__ beta,
                          float* __restrict__ out) {
    int row = blockIdx.x;
    const float2* xr = (const float2*)(x + (size_t)row * Dd);
    int t = threadIdx.x;
    float2 v = xr[t];
    float s1 = v.x + v.y;
    float s2 = v.x * v.x + v.y * v.y;
    #pragma unroll
    for (int o = 16; o; o >>= 1) {
        s1 += __shfl_xor_sync(0xffffffffu, s1, o);
        s2 += __shfl_xor_sync(0xffffffffu, s2, o);
    }
    __shared__ float r1[8], r2[8];
    if ((t & 31) == 0) { r1[t >> 5] = s1; r2[t >> 5] = s2; }
    __syncthreads();
    float S1 = 0.f, S2 = 0.f;
    #pragma unroll
    for (int i = 0; i < 8; i++) { S1 += r1[i]; S2 += r2[i]; }
    float mean = S1 * (1.0f / 512.0f);
    float var  = S2 * (1.0f / 512.0f) - mean * mean;
    float rstd = rsqrtf(var + 1e-5f);
    float2 g  = ((const float2*)gamma)[t];
    float2 bt = ((const float2*)beta)[t];
    float2 o2;
    o2.x = (v.x - mean) * rstd * g.x + bt.x;
    o2.y = (v.y - mean) * rstd * g.y + bt.y;
    ((float2*)(out + (size_t)row * Dd))[t] = o2;
}

// ---------------- double-buffered pipelined GEMM body (round-12) ------------
__device__ __forceinline__ void gemm_body(
        const float* __restrict__ A, const float* __restrict__ W,
        const float* __restrict__ bias, float* __restrict__ C,
        int M, int N, int K, int m0, int n0, float* sm) {
    const int t = threadIdx.x;
    const int warp = t >> 5;
    const int wm = warp & 3, wn = warp >> 2;
    const int lrow = t >> 3, lc = (t & 7) * 4;

    const float* Ap = A + (size_t)(m0 + lrow) * K + lc;
    const float* Wp = W + (size_t)(n0 + lrow) * K + lc;

    float4 av[4], wv[2];
    #pragma unroll
    for (int i = 0; i < 4; i++) av[i] = *(const float4*)(Ap + (size_t)i * 32 * K);
    #pragma unroll
    for (int i = 0; i < 2; i++) wv[i] = *(const float4*)(Wp + (size_t)i * 32 * K);

    wmma::fragment<wmma::accumulator, 16, 16, 8, float> acc[2][2];
    #pragma unroll
    for (int i = 0; i < 2; i++)
        #pragma unroll
        for (int j = 0; j < 2; j++) wmma::fill_fragment(acc[i][j], 0.0f);

    int buf = 0;
    for (int k0 = 0; k0 < K; k0 += 32, buf ^= 1) {
        float* As = sm + buf * 6912;
        float* Bs = As + 128 * 36;
        #pragma unroll
        for (int i = 0; i < 4; i++) {
            float* d = &As[(i * 32 + lrow) * 36 + lc];
            d[0] = f2t(av[i].x); d[1] = f2t(av[i].y);
            d[2] = f2t(av[i].z); d[3] = f2t(av[i].w);
        }
        #pragma unroll
        for (int i = 0; i < 2; i++) {
            float* d = &Bs[(i * 32 + lrow) * 36 + lc];
            d[0] = f2t(wv[i].x); d[1] = f2t(wv[i].y);
            d[2] = f2t(wv[i].z); d[3] = f2t(wv[i].w);
        }
        __syncthreads();
        if (k0 + 32 < K) {
            #pragma unroll
            for (int i = 0; i < 4; i++)
                av[i] = *(const float4*)(Ap + (size_t)i * 32 * K + k0 + 32);
            #pragma unroll
            for (int i = 0; i < 2; i++)
                wv[i] = *(const float4*)(Wp + (size_t)i * 32 * K + k0 + 32);
        }
        #pragma unroll
        for (int kk = 0; kk < 4; kk++) {
            wmma::fragment<wmma::matrix_a, 16, 16, 8, wmma::precision::tf32, wmma::row_major> a[2];
            wmma::fragment<wmma::matrix_b, 16, 16, 8, wmma::precision::tf32, wmma::col_major> b[2];
            wmma::load_matrix_sync(a[0], &As[(wm * 32) * 36 + kk * 8], 36);
            wmma::load_matrix_sync(a[1], &As[(wm * 32 + 16) * 36 + kk * 8], 36);
            wmma::load_matrix_sync(b[0], &Bs[(wn * 32) * 36 + kk * 8], 36);
            wmma::load_matrix_sync(b[1], &Bs[(wn * 32 + 16) * 36 + kk * 8], 36);
            #pragma unroll
            for (int i = 0; i < 2; i++)
                #pragma unroll
                for (int j = 0; j < 2; j++)
                    wmma::mma_sync(acc[i][j], a[i], b[j], acc[i][j]);
        }
    }
    __syncthreads();
    #pragma unroll
    for (int i = 0; i < 2; i++)
        #pragma unroll
        for (int j = 0; j < 2; j++)
            wmma::store_matrix_sync(&sm[(wm * 32 + i * 16) * 68 + wn * 32 + j * 16],
                                    acc[i][j], 68, wmma::mem_row_major);
    __syncthreads();
    #pragma unroll
    for (int i = 0; i < 8; i++) {
        int idx = i * 256 + t, row = idx >> 4, c = (idx & 15) * 4;
        float4 o;
        float b0 = 0.f, b1 = 0.f, b2 = 0.f, b3 = 0.f;
        if (bias) { b0 = bias[n0+c]; b1 = bias[n0+c+1]; b2 = bias[n0+c+2]; b3 = bias[n0+c+3]; }
        o.x = sm[row * 68 + c]     + b0;
        o.y = sm[row * 68 + c + 1] + b1;
        o.z = sm[row * 68 + c + 2] + b2;
        o.w = sm[row * 68 + c + 3] + b3;
        *(float4*)(C + (size_t)(m0 + row) * N + n0 + c) = o;
    }
}

__global__ void __launch_bounds__(256, 2) gemm_nt_wmma(
        const float* __restrict__ A, const float* __restrict__ W,
        const float* __restrict__ bias, float* __restrict__ C,
        int M, int N, int K) {
    extern __shared__ float dsm[];
    gemm_body(A, W, bias, C, M, N, K, blockIdx.y * 128, blockIdx.x * 64, dsm);
}

__global__ void __launch_bounds__(256, 2) gemm_qkv_wmma(
        const float* __restrict__ A,
        const float* __restrict__ W0, const float* __restrict__ W1, const float* __restrict__ W2,
        const float* __restrict__ b0, const float* __restrict__ b1, const float* __restrict__ b2,
        float* __restrict__ C0, float* __restrict__ C1, float* __restrict__ C2) {
    extern __shared__ float dsm[];
    const int z = blockIdx.z;
    const float* W = (z == 0) ? W0 : (z == 1) ? W1 : W2;
    const float* bb = (z == 0) ? b0 : (z == 1) ? b1 : b2;
    float* C = (z == 0) ? C0 : (z == 1) ? C1 : C2;
    gemm_body(A, W, bb, C, 8192, 512, 512, blockIdx.y * 128, blockIdx.x * 64, dsm);
}

// ============ qk with persistent-Q and two t-tiles per block ================
// SMEM: Qs chunks [0, 9216), Ks chunks [9216, 18432). PS stage reuses Ks region.

// ---------------- content QK^T: 2 t-tiles, direct fragment store ------------
__global__ void __launch_bounds__(256, 2) qk_content_wmma(
        const float* __restrict__ q, const float* __restrict__ k,
        const float* __restrict__ ubias, float* __restrict__ out) {
    extern __shared__ float dsm[];
    const int t = threadIdx.x;
    const int warp = t >> 5;
    const int wm = warp & 1, wn = warp >> 1;
    const int bh = blockIdx.z, b = bh >> 3, h = bh & 7;
    const int s0 = blockIdx.y * 128, t0a = blockIdx.x * 256;
    const float* Xb = k + (size_t)b * Ss * Dd;
    const int lrow = t >> 3, lc = (t & 7) * 4;

    const float* Qp = q + (size_t)(b * Ss + s0 + lrow) * Dd + h * 64 + lc;

    // prefetch K chunk 0 (tile 0, kc 0)
    float4 kv[4];
    #pragma unroll
    for (int i = 0; i < 4; i++)
        kv[i] = *(const float4*)(Xb + (size_t)(t0a + i * 32 + lrow) * Dd + h * 64 + lc);

    // stage Q (both kc chunks) once
    #pragma unroll
    for (int kc = 0; kc < 2; kc++) {
        float* Qs = dsm + kc * 4608;
        const float* bb = &ubias[h * 64 + kc * 32 + lc];
        float bb0 = bb[0], bb1 = bb[1], bb2 = bb[2], bb3 = bb[3];
        #pragma unroll
        for (int i = 0; i < 4; i++) {
            float4 qv = *(const float4*)(Qp + (size_t)i * 32 * Dd + kc * 32);
            float* d = &Qs[(i * 32 + lrow) * 36 + lc];
            d[0] = f2t(qv.x + bb0); d[1] = f2t(qv.y + bb1);
            d[2] = f2t(qv.z + bb2); d[3] = f2t(qv.w + bb3);
        }
    }

    wmma::fragment<wmma::accumulator, 16, 16, 8, float> acc[4][2];
    #pragma unroll
    for (int i = 0; i < 4; i++)
        #pragma unroll
        for (int j = 0; j < 2; j++) wmma::fill_fragment(acc[i][j], 0.0f);

    #pragma unroll
    for (int c = 0; c < 4; c++) {
        const int kc = c & 1;
        float* Qs = dsm + kc * 4608;
        float* Ks = dsm + 9216 + kc * 4608;
        #pragma unroll
        for (int i = 0; i < 4; i++) {
            float* e = &Ks[(i * 32 + lrow) * 36 + lc];
            e[0] = f2t(kv[i].x); e[1] = f2t(kv[i].y);
            e[2] = f2t(kv[i].z); e[3] = f2t(kv[i].w);
        }
        __syncthreads();
        if (c < 3) {
            const int cn = c + 1;
            const int nt0 = t0a + (cn >> 1) * 128, nkc = cn & 1;
            #pragma unroll
            for (int i = 0; i < 4; i++)
                kv[i] = *(const float4*)(Xb + (size_t)(nt0 + i * 32 + lrow) * Dd
                                         + h * 64 + nkc * 32 + lc);
        }
        #pragma unroll
        for (int kk = 0; kk < 4; kk++) {
            wmma::fragment<wmma::matrix_a, 16, 16, 8, wmma::precision::tf32, wmma::row_major> a[4];
            wmma::fragment<wmma::matrix_b, 16, 16, 8, wmma::precision::tf32, wmma::col_major> bf[2];
            #pragma unroll
            for (int i = 0; i < 4; i++)
                wmma::load_matrix_sync(a[i], &Qs[(wm * 64 + i * 16) * 36 + kk * 8], 36);
            #pragma unroll
            for (int j = 0; j < 2; j++)
                wmma::load_matrix_sync(bf[j], &Ks[(wn * 32 + j * 16) * 36 + kk * 8], 36);
            #pragma unroll
            for (int i = 0; i < 4; i++)
                #pragma unroll
                for (int j = 0; j < 2; j++)
                    wmma::mma_sync(acc[i][j], a[i], bf[j], acc[i][j]);
        }
        if (kc == 1) {
            const int t0 = t0a + (c >> 1) * 128;
            #pragma unroll
            for (int i = 0; i < 4; i++)
                #pragma unroll
                for (int j = 0; j < 2; j++) {
                    wmma::store_matrix_sync(
                        out + ((size_t)bh * Ss + s0 + wm * 64 + i * 16) * Ss + t0 + wn * 32 + j * 16,
                        acc[i][j], Ss, wmma::mem_row_major);
                    wmma::fill_fragment(acc[i][j], 0.0f);
                }
        }
    }
}

// ---------------- position QK^T: 2 t-tiles, SHIFTED scatter store ------------
__global__ void __launch_bounds__(256, 2) qk_ps_shift_wmma(
        const float* __restrict__ q, const float* __restrict__ pos,
        const float* __restrict__ vbias, float* __restrict__ out) {
    extern __shared__ float dsm[];
    const int t = threadIdx.x;
    const int warp = t >> 5;
    const int wm = warp & 1, wn = warp >> 1;
    const int bh = blockIdx.z, b = bh >> 3, h = bh & 7;
    const int s0 = blockIdx.y * 128, t0a = blockIdx.x * 256;
    const int lrow = t >> 3, lc = (t & 7) * 4;

    const float* Qp = q + (size_t)(b * Ss + s0 + lrow) * Dd + h * 64 + lc;

    float4 kv[4];
    #pragma unroll
    for (int i = 0; i < 4; i++)
        kv[i] = *(const float4*)(pos + (size_t)(t0a + i * 32 + lrow) * Dd + h * 64 + lc);

    #pragma unroll
    for (int kc = 0; kc < 2; kc++) {
        float* Qs = dsm + kc * 4608;
        const float* bb = &vbias[h * 64 + kc * 32 + lc];
        float bb0 = bb[0], bb1 = bb[1], bb2 = bb[2], bb3 = bb[3];
        #pragma unroll
        for (int i = 0; i < 4; i++) {
            float4 qv = *(const float4*)(Qp + (size_t)i * 32 * Dd + kc * 32);
            float* d = &Qs[(i * 32 + lrow) * 36 + lc];
            d[0] = f2t(qv.x + bb0); d[1] = f2t(qv.y + bb1);
            d[2] = f2t(qv.z + bb2); d[3] = f2t(qv.w + bb3);
        }
    }

    wmma::fragment<wmma::accumulator, 16, 16, 8, float> acc[4][2];
    #pragma unroll
    for (int i = 0; i < 4; i++)
        #pragma unroll
        for (int j = 0; j < 2; j++) wmma::fill_fragment(acc[i][j], 0.0f);

    float* stage = dsm + 9216;                  // 128*68 = 8704 <= 9216
    float* obase = out + (size_t)bh * Ss * Ss;

    #pragma unroll
    for (int c = 0; c < 4; c++) {
        const int kc = c & 1;
        float* Qs = dsm + kc * 4608;
        float* Ks = dsm + 9216 + kc * 4608;
        #pragma unroll
        for (int i = 0; i < 4; i++) {
            float* e = &Ks[(i * 32 + lrow) * 36 + lc];
            e[0] = f2t(kv[i].x); e[1] = f2t(kv[i].y);
            e[2] = f2t(kv[i].z); e[3] = f2t(kv[i].w);
        }
        __syncthreads();
        if (c < 3) {
            const int cn = c + 1;
            const int nt0 = t0a + (cn >> 1) * 128, nkc = cn & 1;
            #pragma unroll
            for (int i = 0; i < 4; i++)
                kv[i] = *(const float4*)(pos + (size_t)(nt0 + i * 32 + lrow) * Dd
                                         + h * 64 + nkc * 32 + lc);
        }
        #pragma unroll
        for (int kk = 0; kk < 4; kk++) {
            wmma::fragment<wmma::matrix_a, 16, 16, 8, wmma::precision::tf32, wmma::row_major> a[4];
            wmma::fragment<wmma::matrix_b, 16, 16, 8, wmma::precision::tf32, wmma::col_major> bf[2];
            #pragma unroll
            for (int i = 0; i < 4; i++)
                wmma::load_matrix_sync(a[i], &Qs[(wm * 64 + i * 16) * 36 + kk * 8], 36);
            #pragma unroll
            for (int j = 0; j < 2; j++)
                wmma::load_matrix_sync(bf[j], &Ks[(wn * 32 + j * 16) * 36 + kk * 8], 36);
            #pragma unroll
            for (int i = 0; i < 4; i++)
                #pragma unroll
                for (int j = 0; j < 2; j++)
                    wmma::mma_sync(acc[i][j], a[i], bf[j], acc[i][j]);
        }
        if (kc == 1) {
            // epilogue for tile tt = c>>1: two 64-col waves through the stage
            const int t0 = t0a + (c >> 1) * 128;
            __syncthreads();   // all MMA reads of Ks done before stage reuse
            #pragma unroll
            for (int wave = 0; wave < 2; wave++) {
                if ((wn >> 1) == wave) {
                    #pragma unroll
                    for (int i = 0; i < 4; i++)
                        #pragma unroll
                        for (int j = 0; j < 2; j++)
                            wmma::store_matrix_sync(
                                &stage[(wm * 64 + i * 16) * 68 + (wn & 1) * 32 + j * 16],
                                acc[i][j], 68, wmma::mem_row_major);
                }
                __syncthreads();
                const int ln = t & 31;
                for (int rr = 0; rr < 16; rr++) {
                    int row = warp * 16 + rr;
                    int s = s0 + row;
                    #pragma unroll
                    for (int cc = 0; cc < 2; cc++) {
                        int cidx = ln + cc * 32;
                        int j = t0 + wave * 64 + cidx;
                        float val = stage[row * 68 + cidx];
                        int dr, dc;
                        if (j >= Ss - 1 - s) { dr = s;     dc = j + s + 1 - Ss; }
                        else                 { dr = s - 1; dc = j + s + 1; }
                        if (dr >= 0)
                            obase[(size_t)dr * Ss + dc] = val;
                    }
                }
                __syncthreads();
            }
            #pragma unroll
            for (int i = 0; i < 4; i++)
                #pragma unroll
                for (int j = 0; j < 2; j++) wmma::fill_fragment(acc[i][j], 0.0f);
        }
    }
}

// ---------------- zero the t = s+1 diagonal of shifted ps -------------------
__global__ void diag_zero_kernel(float* __restrict__ psh) {
    int idx = blockIdx.x * 256 + threadIdx.x;
    int s = idx & (Ss - 1);
    if (s < Ss - 1)
        psh[(size_t)idx * Ss + s + 1] = 0.0f;
}

// ---------------- fused ctx (round-13 verbatim) ------------------------------
__global__ void __launch_bounds__(256, 2) ctx_fused_wmma(
        const float* __restrict__ sc, const float* __restrict__ psh,
        const float* __restrict__ v, float* __restrict__ ctx) {
    extern __shared__ float dsm[];
    __shared__ float linv_s[128];
    const int t = threadIdx.x;
    const int warp = t >> 5;
    const int wm = warp & 3, wn = warp >> 2;
    const int bh = blockIdx.z, b = bh >> 3, h = bh & 7;
    const int s0 = blockIdx.y * 128;
    const float scale = 0.04419417382415922f;

    const int lrow = t >> 3, lc = (t & 7) * 4;
    const int vrow = t >> 4, vc = (t & 15) * 4;
    const float* Ap = sc  + ((size_t)bh * Ss + s0 + lrow) * Ss + lc;
    const float* Pp = psh + ((size_t)bh * Ss + s0 + lrow) * Ss + lc;
    const float* Vp = v + ((size_t)(b * Ss + vrow)) * Dd + h * 64 + vc;

    float4 av[4], pv[4], vv[2];
    #pragma unroll
    for (int i = 0; i < 4; i++) {
        av[i] = *(const float4*)(Ap + (size_t)i * 32 * Ss);
        pv[i] = *(const float4*)(Pp + (size_t)i * 32 * Ss);
    }
    #pragma unroll
    for (int i = 0; i < 2; i++) vv[i] = *(const float4*)(Vp + (size_t)i * 16 * Dd);

    wmma::fragment<wmma::accumulator, 16, 16, 8, float> acc[2][2];
    #pragma unroll
    for (int i = 0; i < 2; i++)
        #pragma unroll
        for (int j = 0; j < 2; j++) wmma::fill_fragment(acc[i][j], 0.0f);

    float sums[4] = {0.f, 0.f, 0.f, 0.f};

    int buf = 0;
    for (int k0 = 0; k0 < Ss; k0 += 32, buf ^= 1) {
        float* As = dsm + buf * 6784;
        float* Bs = As + 128 * 36;
        #pragma unroll
        for (int i = 0; i < 4; i++) {
            float e0 = __expf((av[i].x + pv[i].x) * scale);
            float e1 = __expf((av[i].y + pv[i].y) * scale);
            float e2 = __expf((av[i].z + pv[i].z) * scale);
            float e3 = __expf((av[i].w + pv[i].w) * scale);
            sums[i] += e0 + e1 + e2 + e3;
            float* d = &As[(i * 32 + lrow) * 36 + lc];
            d[0] = f2t(e0); d[1] = f2t(e1); d[2] = f2t(e2); d[3] = f2t(e3);
        }
        #pragma unroll
        for (int i = 0; i < 2; i++) {
            float* e = &Bs[(i * 16 + vrow) * 68 + vc];
            e[0] = f2t(vv[i].x); e[1] = f2t(vv[i].y);
            e[2] = f2t(vv[i].z); e[3] = f2t(vv[i].w);
        }
        __syncthreads();
        if (k0 + 32 < Ss) {
            #pragma unroll
            for (int i = 0; i < 4; i++) {
                av[i] = *(const float4*)(Ap + (size_t)i * 32 * Ss + k0 + 32);
                pv[i] = *(const float4*)(Pp + (size_t)i * 32 * Ss + k0 + 32);
            }
            #pragma unroll
            for (int i = 0; i < 2; i++)
                vv[i] = *(const float4*)(Vp + (size_t)(i * 16 + k0 + 32) * Dd);
        }
        #pragma unroll
        for (int kk = 0; kk < 4; kk++) {
            wmma::fragment<wmma::matrix_a, 16, 16, 8, wmma::precision::tf32, wmma::row_major> a[2];
            wmma::fragment<wmma::matrix_b, 16, 16, 8, wmma::precision::tf32, wmma::row_major> bf[2];
            #pragma unroll
            for (int i = 0; i < 2; i++)
                wmma::load_matrix_sync(a[i], &As[(wm * 32 + i * 16) * 36 + kk * 8], 36);
            #pragma unroll
            for (int j = 0; j < 2; j++)
                wmma::load_matrix_sync(bf[j], &Bs[(kk * 8) * 68 + wn * 32 + j * 16], 68);
            #pragma unroll
            for (int i = 0; i < 2; i++)
                #pragma unroll
                for (int j = 0; j < 2; j++)
                    wmma::mma_sync(acc[i][j], a[i], bf[j], acc[i][j]);
        }
    }

    #pragma unroll
    for (int i = 0; i < 4; i++) {
        sums[i] += __shfl_xor_sync(0xffffffffu, sums[i], 1);
        sums[i] += __shfl_xor_sync(0xffffffffu, sums[i], 2);
        sums[i] += __shfl_xor_sync(0xffffffffu, sums[i], 4);
    }
    __syncthreads();
    if ((t & 7) == 0) {
        #pragma unroll
        for (int i = 0; i < 4; i++)
            linv_s[i * 32 + lrow] = 1.0f / sums[i];
    }
    #pragma unroll
    for (int i = 0; i < 2; i++)
        #pragma unroll
        for (int j = 0; j < 2; j++)
            wmma::store_matrix_sync(&dsm[(wm * 32 + i * 16) * 68 + wn * 32 + j * 16],
                                    acc[i][j], 68, wmma::mem_row_major);
    __syncthreads();
    #pragma unroll
    for (int i = 0; i < 8; i++) {
        int idx = i * 256 + t, row = idx >> 4, c = (idx & 15) * 4;
        float li = linv_s[row];
        float4 o;
        o.x = dsm[row * 68 + c]     * li;
        o.y = dsm[row * 68 + c + 1] * li;
        o.z = dsm[row * 68 + c + 2] * li;
        o.w = dsm[row * 68 + c + 3] * li;
        *(float4*)(ctx + (size_t)(b * Ss + s0 + row) * Dd + h * 64 + c) = o;
    }
}

// ---------------- launch -----------------------------------------------------
extern "C" void kernel_launch(void* const* d_in, const int* in_sizes, int n_in,
                              void* d_out, int out_size) {
    const float* inputs = (const float*)d_in[0];
    const float* gamma  = (const float*)d_in[1];
    const float* beta   = (const float*)d_in[2];
    const float* Wq     = (const float*)d_in[3];
    const float* bq     = (const float*)d_in[4];
    const float* Wk     = (const float*)d_in[5];
    const float* bk     = (const float*)d_in[6];
    const float* Wv     = (const float*)d_in[7];
    const float* bv     = (const float*)d_in[8];
    const float* Wpos   = (const float*)d_in[9];
    const float* ub     = (const float*)d_in[10];
    const float* vb     = (const float*)d_in[11];
    const float* Wo     = (const float*)d_in[12];
    const float* bo     = (const float*)d_in[13];
    float* out = (float*)d_out;

    float *xn, *q, *k, *v, *ctx, *pe, *pos, *ps, *sc;
    cudaGetSymbolAddress((void**)&xn,  g_xn);
    cudaGetSymbolAddress((void**)&q,   g_q);
    cudaGetSymbolAddress((void**)&k,   g_k);
    cudaGetSymbolAddress((void**)&v,   g_v);
    cudaGetSymbolAddress((void**)&ctx, g_ctx);
    cudaGetSymbolAddress((void**)&pe,  g_pe);
    cudaGetSymbolAddress((void**)&pos, g_pos);
    cudaGetSymbolAddress((void**)&ps,  g_ps);
    cudaGetSymbolAddress((void**)&sc,  g_sc);

    const int SM_GEMM = 13824 * 4;   // 55296 B
    const int SM_QK   = 18432 * 4;   // 73728 B
    const int SM_CTX  = 13568 * 4;   // 54272 B
    cudaFuncSetAttribute(gemm_nt_wmma,    cudaFuncAttributeMaxDynamicSharedMemorySize, SM_GEMM);
    cudaFuncSetAttribute(gemm_qkv_wmma,   cudaFuncAttributeMaxDynamicSharedMemorySize, SM_GEMM);
    cudaFuncSetAttribute(qk_content_wmma, cudaFuncAttributeMaxDynamicSharedMemorySize, SM_QK);
    cudaFuncSetAttribute(qk_ps_shift_wmma,cudaFuncAttributeMaxDynamicSharedMemorySize, SM_QK);
    cudaFuncSetAttribute(ctx_fused_wmma,  cudaFuncAttributeMaxDynamicSharedMemorySize, SM_CTX);

    pe_kernel<<<2048, 256>>>(pe);
    ln_kernel<<<Bb * Ss, 256>>>(inputs, gamma, beta, xn);

    gemm_qkv_wmma<<<dim3(8, 64, 3), 256, SM_GEMM>>>(xn, Wq, Wk, Wv, bq, bk, bv, q, k, v);
    gemm_nt_wmma<<<dim3(8, 16), 256, SM_GEMM>>>(pe, Wpos, nullptr, pos, 2048, 512, 512);

    qk_content_wmma<<<dim3(8, 16, 32), 256, SM_QK>>>(q, k, ub, sc);
    qk_ps_shift_wmma<<<dim3(8, 16, 32), 256, SM_QK>>>(q, pos, vb, ps);
    diag_zero_kernel<<<Bb * Hh * Ss / 256, 256>>>(ps);

    ctx_fused_wmma<<<dim3(1, 16, 32), 256, SM_CTX>>>(sc, ps, v, ctx);

    gemm_nt_wmma<<<dim3(8, 64), 256, SM_GEMM>>>(ctx, Wo, bo, out, 8192, 512, 512);
}

// round 16
// speedup vs baseline: 2.1364x; 1.4480x over previous
#include <cuda_runtime.h>
#include <cuda_fp16.h>
#include <mma.h>
#include <math.h>
using namespace nvcuda;

#define Bb 4
#define Ss 2048
#define Dd 512
#define Hh 8

// ---------------- scratch ---------------------------------------------------
__device__ float g_xn [Bb*Ss*Dd];
__device__ float g_q  [Bb*Ss*Dd];
__device__ float g_k  [Bb*Ss*Dd];
__device__ float g_v  [Bb*Ss*Dd];
__device__ float g_ctx[Bb*Ss*Dd];
__device__ float g_pe [Ss*Dd];
__device__ float g_pos[Ss*Dd];
__device__ float g_ps [(size_t)Bb*Hh*Ss*Ss];   // SHIFTED position scores
__device__ float g_sc [(size_t)Bb*Hh*Ss*Ss];   // raw content scores

__device__ __forceinline__ float f2t(float x) {
    unsigned r; asm("cvt.rna.tf32.f32 %0, %1;" : "=r"(r) : "f"(x));
    return __uint_as_float(r);
}

// ---------------- sinusoidal positional encoding ---------------------------
__global__ void pe_kernel(float* __restrict__ pe) {
    int idx = blockIdx.x * blockDim.x + threadIdx.x;
    int s = idx >> 8;
    int i = idx & 255;
    float div = expf((2.0f * (float)i) * (-9.210340371976184f / 512.0f));
    float a = (float)s * div;
    pe[s * Dd + 2 * i]     = sinf(a);
    pe[s * Dd + 2 * i + 1] = cosf(a);
}

// ---------------- layernorm -------------------------------------------------
__global__ void ln_kernel(const float* __restrict__ x,
                          const float* __restrict__ gamma,
                          const float* __restrict__ beta,
                          float* __restrict__ out) {
    int row = blockIdx.x;
    const float2* xr = (const float2*)(x + (size_t)row * Dd);
    int t = threadIdx.x;
    float2 v = xr[t];
    float s1 = v.x + v.y;
    float s2 = v.x * v.x + v.y * v.y;
    #pragma unroll
    for (int o = 16; o; o >>= 1) {
        s1 += __shfl_xor_sync(0xffffffffu, s1, o);
        s2 += __shfl_xor_sync(0xffffffffu, s2, o);
    }
    __shared__ float r1[8], r2[8];
    if ((t & 31) == 0) { r1[t >> 5] = s1; r2[t >> 5] = s2; }
    __syncthreads();
    float S1 = 0.f, S2 = 0.f;
    #pragma unroll
    for (int i = 0; i < 8; i++) { S1 += r1[i]; S2 += r2[i]; }
    float mean = S1 * (1.0f / 512.0f);
    float var  = S2 * (1.0f / 512.0f) - mean * mean;
    float rstd = rsqrtf(var + 1e-5f);
    float2 g  = ((const float2*)gamma)[t];
    float2 bt = ((const float2*)beta)[t];
    float2 o2;
    o2.x = (v.x - mean) * rstd * g.x + bt.x;
    o2.y = (v.y - mean) * rstd * g.y + bt.y;
    ((float2*)(out + (size_t)row * Dd))[t] = o2;
}

// ---------------- double-buffered pipelined tf32 GEMM body (round-12) -------
__device__ __forceinline__ void gemm_body(
        const float* __restrict__ A, const float* __restrict__ W,
        const float* __restrict__ bias, float* __restrict__ C,
        int M, int N, int K, int m0, int n0, float* sm) {
    const int t = threadIdx.x;
    const int warp = t >> 5;
    const int wm = warp & 3, wn = warp >> 2;
    const int lrow = t >> 3, lc = (t & 7) * 4;

    const float* Ap = A + (size_t)(m0 + lrow) * K + lc;
    const float* Wp = W + (size_t)(n0 + lrow) * K + lc;

    float4 av[4], wv[2];
    #pragma unroll
    for (int i = 0; i < 4; i++) av[i] = *(const float4*)(Ap + (size_t)i * 32 * K);
    #pragma unroll
    for (int i = 0; i < 2; i++) wv[i] = *(const float4*)(Wp + (size_t)i * 32 * K);

    wmma::fragment<wmma::accumulator, 16, 16, 8, float> acc[2][2];
    #pragma unroll
    for (int i = 0; i < 2; i++)
        #pragma unroll
        for (int j = 0; j < 2; j++) wmma::fill_fragment(acc[i][j], 0.0f);

    int buf = 0;
    for (int k0 = 0; k0 < K; k0 += 32, buf ^= 1) {
        float* As = sm + buf * 6912;
        float* Bs = As + 128 * 36;
        #pragma unroll
        for (int i = 0; i < 4; i++) {
            float* d = &As[(i * 32 + lrow) * 36 + lc];
            d[0] = f2t(av[i].x); d[1] = f2t(av[i].y);
            d[2] = f2t(av[i].z); d[3] = f2t(av[i].w);
        }
        #pragma unroll
        for (int i = 0; i < 2; i++) {
            float* d = &Bs[(i * 32 + lrow) * 36 + lc];
            d[0] = f2t(wv[i].x); d[1] = f2t(wv[i].y);
            d[2] = f2t(wv[i].z); d[3] = f2t(wv[i].w);
        }
        __syncthreads();
        if (k0 + 32 < K) {
            #pragma unroll
            for (int i = 0; i < 4; i++)
                av[i] = *(const float4*)(Ap + (size_t)i * 32 * K + k0 + 32);
            #pragma unroll
            for (int i = 0; i < 2; i++)
                wv[i] = *(const float4*)(Wp + (size_t)i * 32 * K + k0 + 32);
        }
        #pragma unroll
        for (int kk = 0; kk < 4; kk++) {
            wmma::fragment<wmma::matrix_a, 16, 16, 8, wmma::precision::tf32, wmma::row_major> a[2];
            wmma::fragment<wmma::matrix_b, 16, 16, 8, wmma::precision::tf32, wmma::col_major> b[2];
            wmma::load_matrix_sync(a[0], &As[(wm * 32) * 36 + kk * 8], 36);
            wmma::load_matrix_sync(a[1], &As[(wm * 32 + 16) * 36 + kk * 8], 36);
            wmma::load_matrix_sync(b[0], &Bs[(wn * 32) * 36 + kk * 8], 36);
            wmma::load_matrix_sync(b[1], &Bs[(wn * 32 + 16) * 36 + kk * 8], 36);
            #pragma unroll
            for (int i = 0; i < 2; i++)
                #pragma unroll
                for (int j = 0; j < 2; j++)
                    wmma::mma_sync(acc[i][j], a[i], b[j], acc[i][j]);
        }
    }
    __syncthreads();
    #pragma unroll
    for (int i = 0; i < 2; i++)
        #pragma unroll
        for (int j = 0; j < 2; j++)
            wmma::store_matrix_sync(&sm[(wm * 32 + i * 16) * 68 + wn * 32 + j * 16],
                                    acc[i][j], 68, wmma::mem_row_major);
    __syncthreads();
    #pragma unroll
    for (int i = 0; i < 8; i++) {
        int idx = i * 256 + t, row = idx >> 4, c = (idx & 15) * 4;
        float4 o;
        float b0 = 0.f, b1 = 0.f, b2 = 0.f, b3 = 0.f;
        if (bias) { b0 = bias[n0+c]; b1 = bias[n0+c+1]; b2 = bias[n0+c+2]; b3 = bias[n0+c+3]; }
        o.x = sm[row * 68 + c]     + b0;
        o.y = sm[row * 68 + c + 1] + b1;
        o.z = sm[row * 68 + c + 2] + b2;
        o.w = sm[row * 68 + c + 3] + b3;
        *(float4*)(C + (size_t)(m0 + row) * N + n0 + c) = o;
    }
}

__global__ void __launch_bounds__(256, 2) gemm_nt_wmma(
        const float* __restrict__ A, const float* __restrict__ W,
        const float* __restrict__ bias, float* __restrict__ C,
        int M, int N, int K) {
    extern __shared__ float dsm[];
    gemm_body(A, W, bias, C, M, N, K, blockIdx.y * 128, blockIdx.x * 64, dsm);
}

__global__ void __launch_bounds__(256, 2) gemm_qkv_wmma(
        const float* __restrict__ A,
        const float* __restrict__ W0, const float* __restrict__ W1, const float* __restrict__ W2,
        const float* __restrict__ b0, const float* __restrict__ b1, const float* __restrict__ b2,
        float* __restrict__ C0, float* __restrict__ C1, float* __restrict__ C2) {
    extern __shared__ float dsm[];
    const int z = blockIdx.z;
    const float* W = (z == 0) ? W0 : (z == 1) ? W1 : W2;
    const float* bb = (z == 0) ? b0 : (z == 1) ? b1 : b2;
    float* C = (z == 0) ? C0 : (z == 1) ? C1 : C2;
    gemm_body(A, W, bb, C, 8192, 512, 512, blockIdx.y * 128, blockIdx.x * 64, dsm);
}

// ============ fp16 qk: persistent-Q, two t-tiles per block ==================
// SMEM halves: Qs [128][72] @0 (18432 B), Ks buf0 @9216, buf1 @18432 (halves).
// PS float stage (128x68 = 34816 B) overlays the Ks region (36864 B).

// ---------------- content QK^T (fp16 MMA, direct fragment store) ------------
__global__ void __launch_bounds__(256, 2) qk_content_h(
        const float* __restrict__ q, const float* __restrict__ k,
        const float* __restrict__ ubias, float* __restrict__ out) {
    extern __shared__ char dsmc[];
    __half* Qs = (__half*)dsmc;
    const int t = threadIdx.x;
    const int warp = t >> 5;
    const int wm = warp & 1, wn = warp >> 1;
    const int bh = blockIdx.z, b = bh >> 3, h = bh & 7;
    const int s0 = blockIdx.y * 128, t0a = blockIdx.x * 256;
    const float* Xb = k + (size_t)b * Ss * Dd;
    const int lrow = t >> 3, lc = (t & 7) * 4;

    const float* Qp = q + (size_t)(b * Ss + s0 + lrow) * Dd + h * 64 + lc;

    // prefetch K tile0 (full K=64: 8 float4/thread)
    float4 kv[8];
    #pragma unroll
    for (int kc = 0; kc < 2; kc++)
        #pragma unroll
        for (int i = 0; i < 4; i++)
            kv[kc*4+i] = *(const float4*)(Xb + (size_t)(t0a + i*32 + lrow) * Dd
                                          + h * 64 + kc * 32 + lc);

    // stage Q + bias once (fp16)
    #pragma unroll
    for (int kc = 0; kc < 2; kc++) {
        const float* bb = &ubias[h * 64 + kc * 32 + lc];
        float b0 = bb[0], b1 = bb[1], b2 = bb[2], b3 = bb[3];
        #pragma unroll
        for (int i = 0; i < 4; i++) {
            float4 qv = *(const float4*)(Qp + (size_t)i * 32 * Dd + kc * 32);
            __half* d = &Qs[(i*32+lrow)*72 + kc*32 + lc];
            d[0] = __float2half(qv.x + b0); d[1] = __float2half(qv.y + b1);
            d[2] = __float2half(qv.z + b2); d[3] = __float2half(qv.w + b3);
        }
    }

    #pragma unroll
    for (int c = 0; c < 2; c++) {
        __half* Ks = (__half*)dsmc + 9216 + (c & 1) * 9216;
        #pragma unroll
        for (int kc = 0; kc < 2; kc++)
            #pragma unroll
            for (int i = 0; i < 4; i++) {
                float4 v = kv[kc*4+i];
                __half* e = &Ks[(i*32+lrow)*72 + kc*32 + lc];
                e[0] = __float2half(v.x); e[1] = __float2half(v.y);
                e[2] = __float2half(v.z); e[3] = __float2half(v.w);
            }
        __syncthreads();
        if (c == 0) {
            #pragma unroll
            for (int kc = 0; kc < 2; kc++)
                #pragma unroll
                for (int i = 0; i < 4; i++)
                    kv[kc*4+i] = *(const float4*)(Xb + (size_t)(t0a + 128 + i*32 + lrow) * Dd
                                                  + h * 64 + kc * 32 + lc);
        }
        wmma::fragment<wmma::accumulator, 16, 16, 16, float> acc[4][2];
        #pragma unroll
        for (int i = 0; i < 4; i++)
            #pragma unroll
            for (int j = 0; j < 2; j++) wmma::fill_fragment(acc[i][j], 0.0f);
        #pragma unroll
        for (int kk = 0; kk < 4; kk++) {
            wmma::fragment<wmma::matrix_a, 16, 16, 16, __half, wmma::row_major> a[4];
            wmma::fragment<wmma::matrix_b, 16, 16, 16, __half, wmma::col_major> bf[2];
            #pragma unroll
            for (int i = 0; i < 4; i++)
                wmma::load_matrix_sync(a[i], &Qs[(wm*64 + i*16)*72 + kk*16], 72);
            #pragma unroll
            for (int j = 0; j < 2; j++)
                wmma::load_matrix_sync(bf[j], &Ks[(wn*32 + j*16)*72 + kk*16], 72);
            #pragma unroll
            for (int i = 0; i < 4; i++)
                #pragma unroll
                for (int j = 0; j < 2; j++)
                    wmma::mma_sync(acc[i][j], a[i], bf[j], acc[i][j]);
        }
        const int t0 = t0a + c * 128;
        #pragma unroll
        for (int i = 0; i < 4; i++)
            #pragma unroll
            for (int j = 0; j < 2; j++)
                wmma::store_matrix_sync(
                    out + ((size_t)bh * Ss + s0 + wm*64 + i*16) * Ss + t0 + wn*32 + j*16,
                    acc[i][j], Ss, wmma::mem_row_major);
    }
}

// ---------------- position QK^T (fp16 MMA) with SHIFTED scatter store --------
__global__ void __launch_bounds__(256, 2) qk_ps_shift_h(
        const float* __restrict__ q, const float* __restrict__ pos,
        const float* __restrict__ vbias, float* __restrict__ out) {
    extern __shared__ char dsmc[];
    __half* Qs = (__half*)dsmc;
    const int t = threadIdx.x;
    const int warp = t >> 5;
    const int wm = warp & 1, wn = warp >> 1;
    const int bh = blockIdx.z, b = bh >> 3, h = bh & 7;
    const int s0 = blockIdx.y * 128, t0a = blockIdx.x * 256;
    const int lrow = t >> 3, lc = (t & 7) * 4;

    const float* Qp = q + (size_t)(b * Ss + s0 + lrow) * Dd + h * 64 + lc;

    float4 kv[8];
    #pragma unroll
    for (int kc = 0; kc < 2; kc++)
        #pragma unroll
        for (int i = 0; i < 4; i++)
            kv[kc*4+i] = *(const float4*)(pos + (size_t)(t0a + i*32 + lrow) * Dd
                                          + h * 64 + kc * 32 + lc);

    #pragma unroll
    for (int kc = 0; kc < 2; kc++) {
        const float* bb = &vbias[h * 64 + kc * 32 + lc];
        float b0 = bb[0], b1 = bb[1], b2 = bb[2], b3 = bb[3];
        #pragma unroll
        for (int i = 0; i < 4; i++) {
            float4 qv = *(const float4*)(Qp + (size_t)i * 32 * Dd + kc * 32);
            __half* d = &Qs[(i*32+lrow)*72 + kc*32 + lc];
            d[0] = __float2half(qv.x + b0); d[1] = __float2half(qv.y + b1);
            d[2] = __float2half(qv.z + b2); d[3] = __float2half(qv.w + b3);
        }
    }

    float* stage = (float*)(dsmc + 18432);      // overlays both Ks buffers
    float* obase = out + (size_t)bh * Ss * Ss;

    #pragma unroll
    for (int c = 0; c < 2; c++) {
        __half* Ks = (__half*)dsmc + 9216 + (c & 1) * 9216;
        #pragma unroll
        for (int kc = 0; kc < 2; kc++)
            #pragma unroll
            for (int i = 0; i < 4; i++) {
                float4 v = kv[kc*4+i];
                __half* e = &Ks[(i*32+lrow)*72 + kc*32 + lc];
                e[0] = __float2half(v.x); e[1] = __float2half(v.y);
                e[2] = __float2half(v.z); e[3] = __float2half(v.w);
            }
        __syncthreads();
        if (c == 0) {
            #pragma unroll
            for (int kc = 0; kc < 2; kc++)
                #pragma unroll
                for (int i = 0; i < 4; i++)
                    kv[kc*4+i] = *(const float4*)(pos + (size_t)(t0a + 128 + i*32 + lrow) * Dd
                                                  + h * 64 + kc * 32 + lc);
        }
        wmma::fragment<wmma::accumulator, 16, 16, 16, float> acc[4][2];
        #pragma unroll
        for (int i = 0; i < 4; i++)
            #pragma unroll
            for (int j = 0; j < 2; j++) wmma::fill_fragment(acc[i][j], 0.0f);
        #pragma unroll
        for (int kk = 0; kk < 4; kk++) {
            wmma::fragment<wmma::matrix_a, 16, 16, 16, __half, wmma::row_major> a[4];
            wmma::fragment<wmma::matrix_b, 16, 16, 16, __half, wmma::col_major> bf[2];
            #pragma unroll
            for (int i = 0; i < 4; i++)
                wmma::load_matrix_sync(a[i], &Qs[(wm*64 + i*16)*72 + kk*16], 72);
            #pragma unroll
            for (int j = 0; j < 2; j++)
                wmma::load_matrix_sync(bf[j], &Ks[(wn*32 + j*16)*72 + kk*16], 72);
            #pragma unroll
            for (int i = 0; i < 4; i++)
                #pragma unroll
                for (int j = 0; j < 2; j++)
                    wmma::mma_sync(acc[i][j], a[i], bf[j], acc[i][j]);
        }

        // epilogue: two 64-col waves through the float stage, then scatter
        const int t0 = t0a + c * 128;
        __syncthreads();   // all MMA reads of Ks done before stage overwrites
        #pragma unroll
        for (int wave = 0; wave < 2; wave++) {
            if ((wn >> 1) == wave) {
                #pragma unroll
                for (int i = 0; i < 4; i++)
                    #pragma unroll
                    for (int j = 0; j < 2; j++)
                        wmma::store_matrix_sync(
                            &stage[(wm*64 + i*16)*68 + (wn & 1)*32 + j*16],
                            acc[i][j], 68, wmma::mem_row_major);
            }
            __syncthreads();
            const int ln = t & 31;
            for (int rr = 0; rr < 16; rr++) {
                int row = warp * 16 + rr;
                int s = s0 + row;
                #pragma unroll
                for (int cc = 0; cc < 2; cc++) {
                    int cidx = ln + cc * 32;
                    int j = t0 + wave * 64 + cidx;
                    float val = stage[row * 68 + cidx];
                    int dr, dc;
                    if (j >= Ss - 1 - s) { dr = s;     dc = j + s + 1 - Ss; }
                    else                 { dr = s - 1; dc = j + s + 1; }
                    if (dr >= 0)
                        obase[(size_t)dr * Ss + dc] = val;
                }
            }
            __syncthreads();
        }
    }
}

// ---------------- zero the t = s+1 diagonal of shifted ps -------------------
__global__ void diag_zero_kernel(float* __restrict__ psh) {
    int idx = blockIdx.x * 256 + threadIdx.x;
    int s = idx & (Ss - 1);
    if (s < Ss - 1)
        psh[(size_t)idx * Ss + s + 1] = 0.0f;
}

// ---------------- fused ctx (fp16 MMA): P = exp((sc+psh)*scale) -------------
// SMEM halves: per buffer As[128][40] (5120) + Bs[32][72] (2304) = 7424 halves;
// buf0 @0, buf1 @7424. Float O-stage (128x68 = 34816 B) overlays everything.
__global__ void __launch_bounds__(256, 2) ctx_fused_h(
        const float* __restrict__ sc, const float* __restrict__ psh,
        const float* __restrict__ v, float* __restrict__ ctx) {
    extern __shared__ char dsmc[];
    __shared__ float linv_s[128];
    const int t = threadIdx.x;
    const int warp = t >> 5;
    const int wm = warp & 3, wn = warp >> 2;
    const int bh = blockIdx.z, b = bh >> 3, h = bh & 7;
    const int s0 = blockIdx.y * 128;
    const float scale = 0.04419417382415922f;

    const int lrow = t >> 3, lc = (t & 7) * 4;
    const int vrow = t >> 4, vc = (t & 15) * 4;
    const float* Ap = sc  + ((size_t)bh * Ss + s0 + lrow) * Ss + lc;
    const float* Pp = psh + ((size_t)bh * Ss + s0 + lrow) * Ss + lc;
    const float* Vp = v + ((size_t)(b * Ss + vrow)) * Dd + h * 64 + vc;

    float4 av[4], pv[4], vv[2];
    #pragma unroll
    for (int i = 0; i < 4; i++) {
        av[i] = *(const float4*)(Ap + (size_t)i * 32 * Ss);
        pv[i] = *(const float4*)(Pp + (size_t)i * 32 * Ss);
    }
    #pragma unroll
    for (int i = 0; i < 2; i++) vv[i] = *(const float4*)(Vp + (size_t)i * 16 * Dd);

    wmma::fragment<wmma::accumulator, 16, 16, 16, float> acc[2][2];
    #pragma unroll
    for (int i = 0; i < 2; i++)
        #pragma unroll
        for (int j = 0; j < 2; j++) wmma::fill_fragment(acc[i][j], 0.0f);

    float sums[4] = {0.f, 0.f, 0.f, 0.f};

    int buf = 0;
    for (int k0 = 0; k0 < Ss; k0 += 32, buf ^= 1) {
        __half* As = (__half*)dsmc + buf * 7424;
        __half* Bs = As + 5120;
        #pragma unroll
        for (int i = 0; i < 4; i++) {
            float e0 = __expf((av[i].x + pv[i].x) * scale);
            float e1 = __expf((av[i].y + pv[i].y) * scale);
            float e2 = __expf((av[i].z + pv[i].z) * scale);
            float e3 = __expf((av[i].w + pv[i].w) * scale);
            sums[i] += e0 + e1 + e2 + e3;
            __half* d = &As[(i * 32 + lrow) * 40 + lc];
            d[0] = __float2half(e0); d[1] = __float2half(e1);
            d[2] = __float2half(e2); d[3] = __float2half(e3);
        }
        #pragma unroll
        for (int i = 0; i < 2; i++) {
            __half* e = &Bs[(i * 16 + vrow) * 72 + vc];
            e[0] = __float2half(vv[i].x); e[1] = __float2half(vv[i].y);
            e[2] = __float2half(vv[i].z); e[3] = __float2half(vv[i].w);
        }
        __syncthreads();
        if (k0 + 32 < Ss) {
            #pragma unroll
            for (int i = 0; i < 4; i++) {
                av[i] = *(const float4*)(Ap + (size_t)i * 32 * Ss + k0 + 32);
                pv[i] = *(const float4*)(Pp + (size_t)i * 32 * Ss + k0 + 32);
            }
            #pragma unroll
            for (int i = 0; i < 2; i++)
                vv[i] = *(const float4*)(Vp + (size_t)(i * 16 + k0 + 32) * Dd);
        }
        #pragma unroll
        for (int kk = 0; kk < 2; kk++) {
            wmma::fragment<wmma::matrix_a, 16, 16, 16, __half, wmma::row_major> a[2];
            wmma::fragment<wmma::matrix_b, 16, 16, 16, __half, wmma::row_major> bf[2];
            #pragma unroll
            for (int i = 0; i < 2; i++)
                wmma::load_matrix_sync(a[i], &As[(wm * 32 + i * 16) * 40 + kk * 16], 40);
            #pragma unroll
            for (int j = 0; j < 2; j++)
                wmma::load_matrix_sync(bf[j], &Bs[(kk * 16) * 72 + wn * 32 + j * 16], 72);
            #pragma unroll
            for (int i = 0; i < 2; i++)
                #pragma unroll
                for (int j = 0; j < 2; j++)
                    wmma::mma_sync(acc[i][j], a[i], bf[j], acc[i][j]);
        }
    }

    #pragma unroll
    for (int i = 0; i < 4; i++) {
        sums[i] += __shfl_xor_sync(0xffffffffu, sums[i], 1);
        sums[i] += __shfl_xor_sync(0xffffffffu, sums[i], 2);
        sums[i] += __shfl_xor_sync(0xffffffffu, sums[i], 4);
    }
    __syncthreads();
    if ((t & 7) == 0) {
        #pragma unroll
        for (int i = 0; i < 4; i++)
            linv_s[i * 32 + lrow] = 1.0f / sums[i];
    }
    float* ostage = (float*)dsmc;               // 128x68 floats
    #pragma unroll
    for (int i = 0; i < 2; i++)
        #pragma unroll
        for (int j = 0; j < 2; j++)
            wmma::store_matrix_sync(&ostage[(wm * 32 + i * 16) * 68 + wn * 32 + j * 16],
                                    acc[i][j], 68, wmma::mem_row_major);
    __syncthreads();
    #pragma unroll
    for (int i = 0; i < 8; i++) {
        int idx = i * 256 + t, row = idx >> 4, c = (idx & 15) * 4;
        float li = linv_s[row];
        float4 o;
        o.x = ostage[row * 68 + c]     * li;
        o.y = ostage[row * 68 + c + 1] * li;
        o.z = ostage[row * 68 + c + 2] * li;
        o.w = ostage[row * 68 + c + 3] * li;
        *(float4*)(ctx + (size_t)(b * Ss + s0 + row) * Dd + h * 64 + c) = o;
    }
}

// ---------------- launch -----------------------------------------------------
extern "C" void kernel_launch(void* const* d_in, const int* in_sizes, int n_in,
                              void* d_out, int out_size) {
    const float* inputs = (const float*)d_in[0];
    const float* gamma  = (const float*)d_in[1];
    const float* beta   = (const float*)d_in[2];
    const float* Wq     = (const float*)d_in[3];
    const float* bq     = (const float*)d_in[4];
    const float* Wk     = (const float*)d_in[5];
    const float* bk     = (const float*)d_in[6];
    const float* Wv     = (const float*)d_in[7];
    const float* bv     = (const float*)d_in[8];
    const float* Wpos   = (const float*)d_in[9];
    const float* ub     = (const float*)d_in[10];
    const float* vb     = (const float*)d_in[11];
    const float* Wo     = (const float*)d_in[12];
    const float* bo     = (const float*)d_in[13];
    float* out = (float*)d_out;

    float *xn, *q, *k, *v, *ctx, *pe, *pos, *ps, *sc;
    cudaGetSymbolAddress((void**)&xn,  g_xn);
    cudaGetSymbolAddress((void**)&q,   g_q);
    cudaGetSymbolAddress((void**)&k,   g_k);
    cudaGetSymbolAddress((void**)&v,   g_v);
    cudaGetSymbolAddress((void**)&ctx, g_ctx);
    cudaGetSymbolAddress((void**)&pe,  g_pe);
    cudaGetSymbolAddress((void**)&pos, g_pos);
    cudaGetSymbolAddress((void**)&ps,  g_ps);
    cudaGetSymbolAddress((void**)&sc,  g_sc);

    const int SM_GEMM = 13824 * 4;   // 55296 B
    const int SM_QK   = 55296;       // 18432 (Qs) + 36864 (Ks x2 / ps stage)
    const int SM_CTX  = 34816;       // O stage dominates (pipeline needs 29696)
    cudaFuncSetAttribute(gemm_nt_wmma,  cudaFuncAttributeMaxDynamicSharedMemorySize, SM_GEMM);
    cudaFuncSetAttribute(gemm_qkv_wmma, cudaFuncAttributeMaxDynamicSharedMemorySize, SM_GEMM);
    cudaFuncSetAttribute(qk_content_h,  cudaFuncAttributeMaxDynamicSharedMemorySize, SM_QK);
    cudaFuncSetAttribute(qk_ps_shift_h, cudaFuncAttributeMaxDynamicSharedMemorySize, SM_QK);
    cudaFuncSetAttribute(ctx_fused_h,   cudaFuncAttributeMaxDynamicSharedMemorySize, SM_CTX);

    pe_kernel<<<2048, 256>>>(pe);
    ln_kernel<<<Bb * Ss, 256>>>(inputs, gamma, beta, xn);

    gemm_qkv_wmma<<<dim3(8, 64, 3), 256, SM_GEMM>>>(xn, Wq, Wk, Wv, bq, bk, bv, q, k, v);
    gemm_nt_wmma<<<dim3(8, 16), 256, SM_GEMM>>>(pe, Wpos, nullptr, pos, 2048, 512, 512);

    qk_content_h<<<dim3(8, 16, 32), 256, SM_QK>>>(q, k, ub, sc);
    qk_ps_shift_h<<<dim3(8, 16, 32), 256, SM_QK>>>(q, pos, vb, ps);
    diag_zero_kernel<<<Bb * Hh * Ss / 256, 256>>>(ps);

    ctx_fused_h<<<dim3(1, 16, 32), 256, SM_CTX>>>(sc, ps, v, ctx);

    gemm_nt_wmma<<<dim3(8, 64), 256, SM_GEMM>>>(ctx, Wo, bo, out, 8192, 512, 512);
}

// round 17
// speedup vs baseline: 2.7218x; 1.2740x over previous
#include <cuda_runtime.h>
#include <cuda_fp16.h>
#include <mma.h>
#include <math.h>
using namespace nvcuda;

#define Bb 4
#define Ss 2048
#define Dd 512
#define Hh 8

// ---------------- scratch ---------------------------------------------------
__device__ float g_xn [Bb*Ss*Dd];
__device__ float g_q  [Bb*Ss*Dd];
__device__ float g_k  [Bb*Ss*Dd];
__device__ float g_v  [Bb*Ss*Dd];
__device__ float g_ctx[Bb*Ss*Dd];
__device__ float g_pe [Ss*Dd];
__device__ float g_pos[Ss*Dd];
__device__ float g_ps [(size_t)Bb*Hh*Ss*Ss];   // SHIFTED position scores
__device__ float g_sc [(size_t)Bb*Hh*Ss*Ss];   // raw content scores

// ---------------- sinusoidal positional encoding ---------------------------
__global__ void pe_kernel(float* __restrict__ pe) {
    int idx = blockIdx.x * blockDim.x + threadIdx.x;
    int s = idx >> 8;
    int i = idx & 255;
    float div = expf((2.0f * (float)i) * (-9.210340371976184f / 512.0f));
    float a = (float)s * div;
    pe[s * Dd + 2 * i]     = sinf(a);
    pe[s * Dd + 2 * i + 1] = cosf(a);
}

// ---------------- layernorm -------------------------------------------------
__global__ void ln_kernel(const float* __restrict__ x,
                          const float* __restrict__ gamma,
                          const float* __restrict__ beta,
                          float* __restrict__ out) {
    int row = blockIdx.x;
    const float2* xr = (const float2*)(x + (size_t)row * Dd);
    int t = threadIdx.x;
    float2 v = xr[t];
    float s1 = v.x + v.y;
    float s2 = v.x * v.x + v.y * v.y;
    #pragma unroll
    for (int o = 16; o; o >>= 1) {
        s1 += __shfl_xor_sync(0xffffffffu, s1, o);
        s2 += __shfl_xor_sync(0xffffffffu, s2, o);
    }
    __shared__ float r1[8], r2[8];
    if ((t & 31) == 0) { r1[t >> 5] = s1; r2[t >> 5] = s2; }
    __syncthreads();
    float S1 = 0.f, S2 = 0.f;
    #pragma unroll
    for (int i = 0; i < 8; i++) { S1 += r1[i]; S2 += r2[i]; }
    float mean = S1 * (1.0f / 512.0f);
    float var  = S2 * (1.0f / 512.0f) - mean * mean;
    float rstd = rsqrtf(var + 1e-5f);
    float2 g  = ((const float2*)gamma)[t];
    float2 bt = ((const float2*)beta)[t];
    float2 o2;
    o2.x = (v.x - mean) * rstd * g.x + bt.x;
    o2.y = (v.y - mean) * rstd * g.y + bt.y;
    ((float2*)(out + (size_t)row * Dd))[t] = o2;
}

// ---------------- fp16 double-buffered pipelined GEMM body ------------------
// Per buffer: As[128][40] halves (5120) + Bs[64][40] halves (2560) = 7680;
// buf0 @0, buf1 @7680 halves (30720 B total). Float epilogue stage overlays
// (128x68 floats = 34816 B).
__device__ __forceinline__ void gemm_body_h(
        const float* __restrict__ A, const float* __restrict__ W,
        const float* __restrict__ bias, float* __restrict__ C,
        int M, int N, int K, int m0, int n0, char* smc) {
    const int t = threadIdx.x;
    const int warp = t >> 5;
    const int wm = warp & 3, wn = warp >> 2;
    const int lrow = t >> 3, lc = (t & 7) * 4;

    const float* Ap = A + (size_t)(m0 + lrow) * K + lc;
    const float* Wp = W + (size_t)(n0 + lrow) * K + lc;

    float4 av[4], wv[2];
    #pragma unroll
    for (int i = 0; i < 4; i++) av[i] = *(const float4*)(Ap + (size_t)i * 32 * K);
    #pragma unroll
    for (int i = 0; i < 2; i++) wv[i] = *(const float4*)(Wp + (size_t)i * 32 * K);

    wmma::fragment<wmma::accumulator, 16, 16, 16, float> acc[2][2];
    #pragma unroll
    for (int i = 0; i < 2; i++)
        #pragma unroll
        for (int j = 0; j < 2; j++) wmma::fill_fragment(acc[i][j], 0.0f);

    int buf = 0;
    for (int k0 = 0; k0 < K; k0 += 32, buf ^= 1) {
        __half* As = (__half*)smc + buf * 7680;
        __half* Bs = As + 5120;
        #pragma unroll
        for (int i = 0; i < 4; i++) {
            __half* d = &As[(i * 32 + lrow) * 40 + lc];
            d[0] = __float2half(av[i].x); d[1] = __float2half(av[i].y);
            d[2] = __float2half(av[i].z); d[3] = __float2half(av[i].w);
        }
        #pragma unroll
        for (int i = 0; i < 2; i++) {
            __half* d = &Bs[(i * 32 + lrow) * 40 + lc];
            d[0] = __float2half(wv[i].x); d[1] = __float2half(wv[i].y);
            d[2] = __float2half(wv[i].z); d[3] = __float2half(wv[i].w);
        }
        __syncthreads();
        if (k0 + 32 < K) {
            #pragma unroll
            for (int i = 0; i < 4; i++)
                av[i] = *(const float4*)(Ap + (size_t)i * 32 * K + k0 + 32);
            #pragma unroll
            for (int i = 0; i < 2; i++)
                wv[i] = *(const float4*)(Wp + (size_t)i * 32 * K + k0 + 32);
        }
        #pragma unroll
        for (int kk = 0; kk < 2; kk++) {
            wmma::fragment<wmma::matrix_a, 16, 16, 16, __half, wmma::row_major> a[2];
            wmma::fragment<wmma::matrix_b, 16, 16, 16, __half, wmma::col_major> b[2];
            wmma::load_matrix_sync(a[0], &As[(wm * 32) * 40 + kk * 16], 40);
            wmma::load_matrix_sync(a[1], &As[(wm * 32 + 16) * 40 + kk * 16], 40);
            wmma::load_matrix_sync(b[0], &Bs[(wn * 32) * 40 + kk * 16], 40);
            wmma::load_matrix_sync(b[1], &Bs[(wn * 32 + 16) * 40 + kk * 16], 40);
            #pragma unroll
            for (int i = 0; i < 2; i++)
                #pragma unroll
                for (int j = 0; j < 2; j++)
                    wmma::mma_sync(acc[i][j], a[i], b[j], acc[i][j]);
        }
    }
    __syncthreads();
    float* stage = (float*)smc;                 // 128x68 floats
    #pragma unroll
    for (int i = 0; i < 2; i++)
        #pragma unroll
        for (int j = 0; j < 2; j++)
            wmma::store_matrix_sync(&stage[(wm * 32 + i * 16) * 68 + wn * 32 + j * 16],
                                    acc[i][j], 68, wmma::mem_row_major);
    __syncthreads();
    #pragma unroll
    for (int i = 0; i < 8; i++) {
        int idx = i * 256 + t, row = idx >> 4, c = (idx & 15) * 4;
        float4 o;
        float b0 = 0.f, b1 = 0.f, b2 = 0.f, b3 = 0.f;
        if (bias) { b0 = bias[n0+c]; b1 = bias[n0+c+1]; b2 = bias[n0+c+2]; b3 = bias[n0+c+3]; }
        o.x = stage[row * 68 + c]     + b0;
        o.y = stage[row * 68 + c + 1] + b1;
        o.z = stage[row * 68 + c + 2] + b2;
        o.w = stage[row * 68 + c + 3] + b3;
        *(float4*)(C + (size_t)(m0 + row) * N + n0 + c) = o;
    }
}

__global__ void __launch_bounds__(256, 2) gemm_nt_h(
        const float* __restrict__ A, const float* __restrict__ W,
        const float* __restrict__ bias, float* __restrict__ C,
        int M, int N, int K) {
    extern __shared__ char dsmc[];
    gemm_body_h(A, W, bias, C, M, N, K, blockIdx.y * 128, blockIdx.x * 64, dsmc);
}

__global__ void __launch_bounds__(256, 2) gemm_qkv_h(
        const float* __restrict__ A,
        const float* __restrict__ W0, const float* __restrict__ W1, const float* __restrict__ W2,
        const float* __restrict__ b0, const float* __restrict__ b1, const float* __restrict__ b2,
        float* __restrict__ C0, float* __restrict__ C1, float* __restrict__ C2) {
    extern __shared__ char dsmc[];
    const int z = blockIdx.z;
    const float* W = (z == 0) ? W0 : (z == 1) ? W1 : W2;
    const float* bb = (z == 0) ? b0 : (z == 1) ? b1 : b2;
    float* C = (z == 0) ? C0 : (z == 1) ? C1 : C2;
    gemm_body_h(A, W, bb, C, 8192, 512, 512, blockIdx.y * 128, blockIdx.x * 64, dsmc);
}

// ============ fp16 qk: persistent-Q, two t-tiles per block (round-16) =======

// ---------------- content QK^T (fp16 MMA, direct fragment store) ------------
__global__ void __launch_bounds__(256, 2) qk_content_h(
        const float* __restrict__ q, const float* __restrict__ k,
        const float* __restrict__ ubias, float* __restrict__ out) {
    extern __shared__ char dsmc[];
    __half* Qs = (__half*)dsmc;
    const int t = threadIdx.x;
    const int warp = t >> 5;
    const int wm = warp & 1, wn = warp >> 1;
    const int bh = blockIdx.z, b = bh >> 3, h = bh & 7;
    const int s0 = blockIdx.y * 128, t0a = blockIdx.x * 256;
    const float* Xb = k + (size_t)b * Ss * Dd;
    const int lrow = t >> 3, lc = (t & 7) * 4;

    const float* Qp = q + (size_t)(b * Ss + s0 + lrow) * Dd + h * 64 + lc;

    float4 kv[8];
    #pragma unroll
    for (int kc = 0; kc < 2; kc++)
        #pragma unroll
        for (int i = 0; i < 4; i++)
            kv[kc*4+i] = *(const float4*)(Xb + (size_t)(t0a + i*32 + lrow) * Dd
                                          + h * 64 + kc * 32 + lc);

    #pragma unroll
    for (int kc = 0; kc < 2; kc++) {
        const float* bb = &ubias[h * 64 + kc * 32 + lc];
        float b0 = bb[0], b1 = bb[1], b2 = bb[2], b3 = bb[3];
        #pragma unroll
        for (int i = 0; i < 4; i++) {
            float4 qv = *(const float4*)(Qp + (size_t)i * 32 * Dd + kc * 32);
            __half* d = &Qs[(i*32+lrow)*72 + kc*32 + lc];
            d[0] = __float2half(qv.x + b0); d[1] = __float2half(qv.y + b1);
            d[2] = __float2half(qv.z + b2); d[3] = __float2half(qv.w + b3);
        }
    }

    #pragma unroll
    for (int c = 0; c < 2; c++) {
        __half* Ks = (__half*)dsmc + 9216 + (c & 1) * 9216;
        #pragma unroll
        for (int kc = 0; kc < 2; kc++)
            #pragma unroll
            for (int i = 0; i < 4; i++) {
                float4 v = kv[kc*4+i];
                __half* e = &Ks[(i*32+lrow)*72 + kc*32 + lc];
                e[0] = __float2half(v.x); e[1] = __float2half(v.y);
                e[2] = __float2half(v.z); e[3] = __float2half(v.w);
            }
        __syncthreads();
        if (c == 0) {
            #pragma unroll
            for (int kc = 0; kc < 2; kc++)
                #pragma unroll
                for (int i = 0; i < 4; i++)
                    kv[kc*4+i] = *(const float4*)(Xb + (size_t)(t0a + 128 + i*32 + lrow) * Dd
                                                  + h * 64 + kc * 32 + lc);
        }
        wmma::fragment<wmma::accumulator, 16, 16, 16, float> acc[4][2];
        #pragma unroll
        for (int i = 0; i < 4; i++)
            #pragma unroll
            for (int j = 0; j < 2; j++) wmma::fill_fragment(acc[i][j], 0.0f);
        #pragma unroll
        for (int kk = 0; kk < 4; kk++) {
            wmma::fragment<wmma::matrix_a, 16, 16, 16, __half, wmma::row_major> a[4];
            wmma::fragment<wmma::matrix_b, 16, 16, 16, __half, wmma::col_major> bf[2];
            #pragma unroll
            for (int i = 0; i < 4; i++)
                wmma::load_matrix_sync(a[i], &Qs[(wm*64 + i*16)*72 + kk*16], 72);
            #pragma unroll
            for (int j = 0; j < 2; j++)
                wmma::load_matrix_sync(bf[j], &Ks[(wn*32 + j*16)*72 + kk*16], 72);
            #pragma unroll
            for (int i = 0; i < 4; i++)
                #pragma unroll
                for (int j = 0; j < 2; j++)
                    wmma::mma_sync(acc[i][j], a[i], bf[j], acc[i][j]);
        }
        const int t0 = t0a + c * 128;
        #pragma unroll
        for (int i = 0; i < 4; i++)
            #pragma unroll
            for (int j = 0; j < 2; j++)
                wmma::store_matrix_sync(
                    out + ((size_t)bh * Ss + s0 + wm*64 + i*16) * Ss + t0 + wn*32 + j*16,
                    acc[i][j], Ss, wmma::mem_row_major);
    }
}

// ---------------- position QK^T (fp16 MMA) with SHIFTED scatter store --------
__global__ void __launch_bounds__(256, 2) qk_ps_shift_h(
        const float* __restrict__ q, const float* __restrict__ pos,
        const float* __restrict__ vbias, float* __restrict__ out) {
    extern __shared__ char dsmc[];
    __half* Qs = (__half*)dsmc;
    const int t = threadIdx.x;
    const int warp = t >> 5;
    const int wm = warp & 1, wn = warp >> 1;
    const int bh = blockIdx.z, b = bh >> 3, h = bh & 7;
    const int s0 = blockIdx.y * 128, t0a = blockIdx.x * 256;
    const int lrow = t >> 3, lc = (t & 7) * 4;

    const float* Qp = q + (size_t)(b * Ss + s0 + lrow) * Dd + h * 64 + lc;

    float4 kv[8];
    #pragma unroll
    for (int kc = 0; kc < 2; kc++)
        #pragma unroll
        for (int i = 0; i < 4; i++)
            kv[kc*4+i] = *(const float4*)(pos + (size_t)(t0a + i*32 + lrow) * Dd
                                          + h * 64 + kc * 32 + lc);

    #pragma unroll
    for (int kc = 0; kc < 2; kc++) {
        const float* bb = &vbias[h * 64 + kc * 32 + lc];
        float b0 = bb[0], b1 = bb[1], b2 = bb[2], b3 = bb[3];
        #pragma unroll
        for (int i = 0; i < 4; i++) {
            float4 qv = *(const float4*)(Qp + (size_t)i * 32 * Dd + kc * 32);
            __half* d = &Qs[(i*32+lrow)*72 + kc*32 + lc];
            d[0] = __float2half(qv.x + b0); d[1] = __float2half(qv.y + b1);
            d[2] = __float2half(qv.z + b2); d[3] = __float2half(qv.w + b3);
        }
    }

    float* stage = (float*)(dsmc + 18432);
    float* obase = out + (size_t)bh * Ss * Ss;

    #pragma unroll
    for (int c = 0; c < 2; c++) {
        __half* Ks = (__half*)dsmc + 9216 + (c & 1) * 9216;
        #pragma unroll
        for (int kc = 0; kc < 2; kc++)
            #pragma unroll
            for (int i = 0; i < 4; i++) {
                float4 v = kv[kc*4+i];
                __half* e = &Ks[(i*32+lrow)*72 + kc*32 + lc];
                e[0] = __float2half(v.x); e[1] = __float2half(v.y);
                e[2] = __float2half(v.z); e[3] = __float2half(v.w);
            }
        __syncthreads();
        if (c == 0) {
            #pragma unroll
            for (int kc = 0; kc < 2; kc++)
                #pragma unroll
                for (int i = 0; i < 4; i++)
                    kv[kc*4+i] = *(const float4*)(pos + (size_t)(t0a + 128 + i*32 + lrow) * Dd
                                                  + h * 64 + kc * 32 + lc);
        }
        wmma::fragment<wmma::accumulator, 16, 16, 16, float> acc[4][2];
        #pragma unroll
        for (int i = 0; i < 4; i++)
            #pragma unroll
            for (int j = 0; j < 2; j++) wmma::fill_fragment(acc[i][j], 0.0f);
        #pragma unroll
        for (int kk = 0; kk < 4; kk++) {
            wmma::fragment<wmma::matrix_a, 16, 16, 16, __half, wmma::row_major> a[4];
            wmma::fragment<wmma::matrix_b, 16, 16, 16, __half, wmma::col_major> bf[2];
            #pragma unroll
            for (int i = 0; i < 4; i++)
                wmma::load_matrix_sync(a[i], &Qs[(wm*64 + i*16)*72 + kk*16], 72);
            #pragma unroll
            for (int j = 0; j < 2; j++)
                wmma::load_matrix_sync(bf[j], &Ks[(wn*32 + j*16)*72 + kk*16], 72);
            #pragma unroll
            for (int i = 0; i < 4; i++)
                #pragma unroll
                for (int j = 0; j < 2; j++)
                    wmma::mma_sync(acc[i][j], a[i], bf[j], acc[i][j]);
        }

        const int t0 = t0a + c * 128;
        __syncthreads();
        #pragma unroll
        for (int wave = 0; wave < 2; wave++) {
            if ((wn >> 1) == wave) {
                #pragma unroll
                for (int i = 0; i < 4; i++)
                    #pragma unroll
                    for (int j = 0; j < 2; j++)
                        wmma::store_matrix_sync(
                            &stage[(wm*64 + i*16)*68 + (wn & 1)*32 + j*16],
                            acc[i][j], 68, wmma::mem_row_major);
            }
            __syncthreads();
            const int ln = t & 31;
            for (int rr = 0; rr < 16; rr++) {
                int row = warp * 16 + rr;
                int s = s0 + row;
                #pragma unroll
                for (int cc = 0; cc < 2; cc++) {
                    int cidx = ln + cc * 32;
                    int j = t0 + wave * 64 + cidx;
                    float val = stage[row * 68 + cidx];
                    int dr, dc;
                    if (j >= Ss - 1 - s) { dr = s;     dc = j + s + 1 - Ss; }
                    else                 { dr = s - 1; dc = j + s + 1; }
                    if (dr >= 0)
                        obase[(size_t)dr * Ss + dc] = val;
                }
            }
            __syncthreads();
        }
    }
}

// ---------------- zero the t = s+1 diagonal of shifted ps -------------------
__global__ void diag_zero_kernel(float* __restrict__ psh) {
    int idx = blockIdx.x * 256 + threadIdx.x;
    int s = idx & (Ss - 1);
    if (s < Ss - 1)
        psh[(size_t)idx * Ss + s + 1] = 0.0f;
}

// ---------------- fused ctx (fp16 MMA, round-16 verbatim) -------------------
__global__ void __launch_bounds__(256, 2) ctx_fused_h(
        const float* __restrict__ sc, const float* __restrict__ psh,
        const float* __restrict__ v, float* __restrict__ ctx) {
    extern __shared__ char dsmc[];
    __shared__ float linv_s[128];
    const int t = threadIdx.x;
    const int warp = t >> 5;
    const int wm = warp & 3, wn = warp >> 2;
    const int bh = blockIdx.z, b = bh >> 3, h = bh & 7;
    const int s0 = blockIdx.y * 128;
    const float scale = 0.04419417382415922f;

    const int lrow = t >> 3, lc = (t & 7) * 4;
    const int vrow = t >> 4, vc = (t & 15) * 4;
    const float* Ap = sc  + ((size_t)bh * Ss + s0 + lrow) * Ss + lc;
    const float* Pp = psh + ((size_t)bh * Ss + s0 + lrow) * Ss + lc;
    const float* Vp = v + ((size_t)(b * Ss + vrow)) * Dd + h * 64 + vc;

    float4 av[4], pv[4], vv[2];
    #pragma unroll
    for (int i = 0; i < 4; i++) {
        av[i] = *(const float4*)(Ap + (size_t)i * 32 * Ss);
        pv[i] = *(const float4*)(Pp + (size_t)i * 32 * Ss);
    }
    #pragma unroll
    for (int i = 0; i < 2; i++) vv[i] = *(const float4*)(Vp + (size_t)i * 16 * Dd);

    wmma::fragment<wmma::accumulator, 16, 16, 16, float> acc[2][2];
    #pragma unroll
    for (int i = 0; i < 2; i++)
        #pragma unroll
        for (int j = 0; j < 2; j++) wmma::fill_fragment(acc[i][j], 0.0f);

    float sums[4] = {0.f, 0.f, 0.f, 0.f};

    int buf = 0;
    for (int k0 = 0; k0 < Ss; k0 += 32, buf ^= 1) {
        __half* As = (__half*)dsmc + buf * 7424;
        __half* Bs = As + 5120;
        #pragma unroll
        for (int i = 0; i < 4; i++) {
            float e0 = __expf((av[i].x + pv[i].x) * scale);
            float e1 = __expf((av[i].y + pv[i].y) * scale);
            float e2 = __expf((av[i].z + pv[i].z) * scale);
            float e3 = __expf((av[i].w + pv[i].w) * scale);
            sums[i] += e0 + e1 + e2 + e3;
            __half* d = &As[(i * 32 + lrow) * 40 + lc];
            d[0] = __float2half(e0); d[1] = __float2half(e1);
            d[2] = __float2half(e2); d[3] = __float2half(e3);
        }
        #pragma unroll
        for (int i = 0; i < 2; i++) {
            __half* e = &Bs[(i * 16 + vrow) * 72 + vc];
            e[0] = __float2half(vv[i].x); e[1] = __float2half(vv[i].y);
            e[2] = __float2half(vv[i].z); e[3] = __float2half(vv[i].w);
        }
        __syncthreads();
        if (k0 + 32 < Ss) {
            #pragma unroll
            for (int i = 0; i < 4; i++) {
                av[i] = *(const float4*)(Ap + (size_t)i * 32 * Ss + k0 + 32);
                pv[i] = *(const float4*)(Pp + (size_t)i * 32 * Ss + k0 + 32);
            }
            #pragma unroll
            for (int i = 0; i < 2; i++)
                vv[i] = *(const float4*)(Vp + (size_t)(i * 16 + k0 + 32) * Dd);
        }
        #pragma unroll
        for (int kk = 0; kk < 2; kk++) {
            wmma::fragment<wmma::matrix_a, 16, 16, 16, __half, wmma::row_major> a[2];
            wmma::fragment<wmma::matrix_b, 16, 16, 16, __half, wmma::row_major> bf[2];
            #pragma unroll
            for (int i = 0; i < 2; i++)
                wmma::load_matrix_sync(a[i], &As[(wm * 32 + i * 16) * 40 + kk * 16], 40);
            #pragma unroll
            for (int j = 0; j < 2; j++)
                wmma::load_matrix_sync(bf[j], &Bs[(kk * 16) * 72 + wn * 32 + j * 16], 72);
            #pragma unroll
            for (int i = 0; i < 2; i++)
                #pragma unroll
                for (int j = 0; j < 2; j++)
                    wmma::mma_sync(acc[i][j], a[i], bf[j], acc[i][j]);
        }
    }

    #pragma unroll
    for (int i = 0; i < 4; i++) {
        sums[i] += __shfl_xor_sync(0xffffffffu, sums[i], 1);
        sums[i] += __shfl_xor_sync(0xffffffffu, sums[i], 2);
        sums[i] += __shfl_xor_sync(0xffffffffu, sums[i], 4);
    }
    __syncthreads();
    if ((t & 7) == 0) {
        #pragma unroll
        for (int i = 0; i < 4; i++)
            linv_s[i * 32 + lrow] = 1.0f / sums[i];
    }
    float* ostage = (float*)dsmc;
    #pragma unroll
    for (int i = 0; i < 2; i++)
        #pragma unroll
        for (int j = 0; j < 2; j++)
            wmma::store_matrix_sync(&ostage[(wm * 32 + i * 16) * 68 + wn * 32 + j * 16],
                                    acc[i][j], 68, wmma::mem_row_major);
    __syncthreads();
    #pragma unroll
    for (int i = 0; i < 8; i++) {
        int idx = i * 256 + t, row = idx >> 4, c = (idx & 15) * 4;
        float li = linv_s[row];
        float4 o;
        o.x = ostage[row * 68 + c]     * li;
        o.y = ostage[row * 68 + c + 1] * li;
        o.z = ostage[row * 68 + c + 2] * li;
        o.w = ostage[row * 68 + c + 3] * li;
        *(float4*)(ctx + (size_t)(b * Ss + s0 + row) * Dd + h * 64 + c) = o;
    }
}

// ---------------- launch -----------------------------------------------------
extern "C" void kernel_launch(void* const* d_in, const int* in_sizes, int n_in,
                              void* d_out, int out_size) {
    const float* inputs = (const float*)d_in[0];
    const float* gamma  = (const float*)d_in[1];
    const float* beta   = (const float*)d_in[2];
    const float* Wq     = (const float*)d_in[3];
    const float* bq     = (const float*)d_in[4];
    const float* Wk     = (const float*)d_in[5];
    const float* bk     = (const float*)d_in[6];
    const float* Wv     = (const float*)d_in[7];
    const float* bv     = (const float*)d_in[8];
    const float* Wpos   = (const float*)d_in[9];
    const float* ub     = (const float*)d_in[10];
    const float* vb     = (const float*)d_in[11];
    const float* Wo     = (const float*)d_in[12];
    const float* bo     = (const float*)d_in[13];
    float* out = (float*)d_out;

    float *xn, *q, *k, *v, *ctx, *pe, *pos, *ps, *sc;
    cudaGetSymbolAddress((void**)&xn,  g_xn);
    cudaGetSymbolAddress((void**)&q,   g_q);
    cudaGetSymbolAddress((void**)&k,   g_k);
    cudaGetSymbolAddress((void**)&v,   g_v);
    cudaGetSymbolAddress((void**)&ctx, g_ctx);
    cudaGetSymbolAddress((void**)&pe,  g_pe);
    cudaGetSymbolAddress((void**)&pos, g_pos);
    cudaGetSymbolAddress((void**)&ps,  g_ps);
    cudaGetSymbolAddress((void**)&sc,  g_sc);

    const int SM_GEMM = 34816;       // float stage dominates (pipeline 30720)
    const int SM_QK   = 55296;       // 18432 (Qs) + 36864 (Ks x2 / ps stage)
    const int SM_CTX  = 34816;
    cudaFuncSetAttribute(gemm_nt_h,     cudaFuncAttributeMaxDynamicSharedMemorySize, SM_GEMM);
    cudaFuncSetAttribute(gemm_qkv_h,    cudaFuncAttributeMaxDynamicSharedMemorySize, SM_GEMM);
    cudaFuncSetAttribute(qk_content_h,  cudaFuncAttributeMaxDynamicSharedMemorySize, SM_QK);
    cudaFuncSetAttribute(qk_ps_shift_h, cudaFuncAttributeMaxDynamicSharedMemorySize, SM_QK);
    cudaFuncSetAttribute(ctx_fused_h,   cudaFuncAttributeMaxDynamicSharedMemorySize, SM_CTX);

    pe_kernel<<<2048, 256>>>(pe);
    ln_kernel<<<Bb * Ss, 256>>>(inputs, gamma, beta, xn);

    gemm_qkv_h<<<dim3(8, 64, 3), 256, SM_GEMM>>>(xn, Wq, Wk, Wv, bq, bk, bv, q, k, v);
    gemm_nt_h<<<dim3(8, 16), 256, SM_GEMM>>>(pe, Wpos, nullptr, pos, 2048, 512, 512);

    qk_content_h<<<dim3(8, 16, 32), 256, SM_QK>>>(q, k, ub, sc);
    qk_ps_shift_h<<<dim3(8, 16, 32), 256, SM_QK>>>(q, pos, vb, ps);
    diag_zero_kernel<<<Bb * Hh * Ss / 256, 256>>>(ps);

    ctx_fused_h<<<dim3(1, 16, 32), 256, SM_CTX>>>(sc, ps, v, ctx);

    gemm_nt_h<<<dim3(8, 64), 256, SM_GEMM>>>(ctx, Wo, bo, out, 8192, 512, 512);
}